// round 1
// baseline (speedup 1.0000x reference)
#include <cuda_runtime.h>
#include <math.h>

#define NN 8192
#define FIN 3000
#define FO 64
#define CAP 192

// ---------------- scratch (__device__ globals; no allocation allowed) ----------------
__device__ int   g_adj_idx[NN * CAP];
__device__ int   g_adj_cnt[NN];
__device__ float g_dinv[NN];
__device__ int   g_gn_idx[NN * CAP];
__device__ int   g_gn_cnt[NN];
__device__ float g_xw1[NN * FO];    // feat  @ W1
__device__ float g_xaw1[NN * FO];   // feat_a @ W1
__device__ float g_pz[NN * FO];     // P @ z
__device__ float g_gv[NN * FO];     // g   (sigmoid(normalized readout)) for feat
__device__ float g_gva[NN * FO];    // g_a

// ---------------------------------------------------------------------------
// Build ELL index list from a dense binary row. which=0: adj (append self
// loop, compute dinv = rsqrt(deg)). which=1: graph_neigh (diag already 1 in
// input; no append). Deterministic: per-thread contiguous 32-col chunks +
// serial block scan -> list sorted ascending by column.
// ---------------------------------------------------------------------------
__global__ void build_list_kernel(const float* __restrict__ mat, int which)
{
    int row = blockIdx.x;
    int t   = threadIdx.x;   // 256 threads
    const float4* rp = reinterpret_cast<const float4*>(mat + (size_t)row * NN);
    int base = t * 8;        // 8 float4 = 32 columns per thread

    int c = 0;
    #pragma unroll
    for (int q = 0; q < 8; q++) {
        float4 v = rp[base + q];
        c += (v.x != 0.f) + (v.y != 0.f) + (v.z != 0.f) + (v.w != 0.f);
    }

    __shared__ int counts[256];
    __shared__ int total;
    counts[t] = c;
    __syncthreads();
    if (t == 0) {
        int s = 0;
        for (int i = 0; i < 256; i++) { int cc = counts[i]; counts[i] = s; s += cc; }
        total = s;
    }
    __syncthreads();

    int o = counts[t];
    int* out = (which ? g_gn_idx : g_adj_idx) + (size_t)row * CAP;
    #pragma unroll
    for (int q = 0; q < 8; q++) {
        float4 v = rp[base + q];   // re-read: hits L1/L2
        int j0 = (base + q) * 4;
        if (v.x != 0.f && o < CAP) out[o++] = j0;
        if (v.y != 0.f && o < CAP) out[o++] = j0 + 1;
        if (v.z != 0.f && o < CAP) out[o++] = j0 + 2;
        if (v.w != 0.f && o < CAP) out[o++] = j0 + 3;
    }
    if (t == 0) {
        int tot = total;
        if (which == 0) {
            if (tot < CAP) { out[tot] = row; tot++; }   // self loop
            g_adj_cnt[row] = tot;
            g_dinv[row]    = rsqrtf((float)tot);        // deg = nnz + self
        } else {
            g_gn_cnt[row] = tot;
        }
    }
}

// ---------------------------------------------------------------------------
// XW = feat @ W1 (and feat_a @ W1 via blockIdx.z). M=8192 K=3000 N=64.
// 128x64 block tile, 8x4 per-thread tile, BK=32.
// ---------------------------------------------------------------------------
__global__ void gemm_feat_kernel(const float* __restrict__ feat,
                                 const float* __restrict__ feat_a,
                                 const float* __restrict__ W1)
{
    __shared__ float As[128 * 32];
    __shared__ float Bs[32 * 64];
    const float* A = blockIdx.z ? feat_a : feat;
    float*       C = blockIdx.z ? g_xaw1 : g_xw1;
    int row0 = blockIdx.x * 128;
    int tid = threadIdx.x;
    int tx = tid & 15, ty = tid >> 4;

    float acc[8][4];
    #pragma unroll
    for (int i = 0; i < 8; i++)
        #pragma unroll
        for (int j = 0; j < 4; j++) acc[i][j] = 0.f;

    for (int k0 = 0; k0 < FIN; k0 += 32) {
        #pragma unroll
        for (int i = 0; i < 16; i++) {          // 128x32 A tile
            int l = tid + i * 256;
            int r = l >> 5, k = l & 31;
            int gk = k0 + k;
            As[l] = (gk < FIN) ? A[(size_t)(row0 + r) * FIN + gk] : 0.f;
        }
        #pragma unroll
        for (int i = 0; i < 8; i++) {           // 32x64 B tile
            int l = tid + i * 256;
            int k = l >> 6, n = l & 63;
            int gk = k0 + k;
            Bs[l] = (gk < FIN) ? W1[(size_t)gk * FO + n] : 0.f;
        }
        __syncthreads();
        #pragma unroll
        for (int k = 0; k < 32; k++) {
            float a[8];
            #pragma unroll
            for (int i = 0; i < 8; i++) a[i] = As[(ty * 8 + i) * 32 + k];
            float4 b4 = *reinterpret_cast<const float4*>(&Bs[k * 64 + tx * 4]);
            float b[4] = {b4.x, b4.y, b4.z, b4.w};
            #pragma unroll
            for (int i = 0; i < 8; i++)
                #pragma unroll
                for (int j = 0; j < 4; j++)
                    acc[i][j] += a[i] * b[j];
        }
        __syncthreads();
    }
    #pragma unroll
    for (int i = 0; i < 8; i++) {
        int r = row0 + ty * 8 + i;
        float4 v = make_float4(acc[i][0], acc[i][1], acc[i][2], acc[i][3]);
        *reinterpret_cast<float4*>(&C[(size_t)r * FO + tx * 4]) = v;
    }
}

// ---------------------------------------------------------------------------
// z = P @ XW1 ; emb = relu(z) ; emb_a = relu(P @ XaW1).
// One block per row, 64 threads (one per output column).
// ---------------------------------------------------------------------------
__global__ void spmm1_kernel(float* __restrict__ out_z, float* __restrict__ out_emb,
                             float* __restrict__ out_emb_a)
{
    int row = blockIdx.x, t = threadIdx.x;
    __shared__ int   sidx[CAP];
    __shared__ float sw[CAP];
    int cnt = g_adj_cnt[row];
    for (int k = t; k < cnt; k += 64) {
        int j = g_adj_idx[(size_t)row * CAP + k];
        sidx[k] = j;
        sw[k]   = g_dinv[j];
    }
    __syncthreads();
    float acc = 0.f, acca = 0.f;
    for (int k = 0; k < cnt; k++) {
        int j = sidx[k]; float w = sw[k];
        acc  += w * g_xw1[(size_t)j * FO + t];
        acca += w * g_xaw1[(size_t)j * FO + t];
    }
    float di = g_dinv[row];
    float z = di * acc, za = di * acca;
    out_z[(size_t)row * FO + t]     = z;
    out_emb[(size_t)row * FO + t]   = fmaxf(z, 0.f);
    out_emb_a[(size_t)row * FO + t] = fmaxf(za, 0.f);
}

// Pz = P @ z
__global__ void spmm2_kernel(const float* __restrict__ z)
{
    int row = blockIdx.x, t = threadIdx.x;
    __shared__ int   sidx[CAP];
    __shared__ float sw[CAP];
    int cnt = g_adj_cnt[row];
    for (int k = t; k < cnt; k += 64) {
        int j = g_adj_idx[(size_t)row * CAP + k];
        sidx[k] = j;
        sw[k]   = g_dinv[j];
    }
    __syncthreads();
    float acc = 0.f;
    for (int k = 0; k < cnt; k++)
        acc += sw[k] * z[(size_t)sidx[k] * FO + t];
    g_pz[(size_t)row * FO + t] = g_dinv[row] * acc;
}

// ---------------------------------------------------------------------------
// h = Pz @ W2. M=8192 K=64 N=3000. 64x128 block tile, 4x8 per-thread.
// ---------------------------------------------------------------------------
__global__ void gemm_h_kernel(const float* __restrict__ W2, float* __restrict__ outh)
{
    __shared__ float As[64 * 32];
    __shared__ float Bs[32 * 128];
    int row0 = blockIdx.x * 64;
    int n0   = blockIdx.y * 128;
    int tid = threadIdx.x;
    int tx = tid & 15, ty = tid >> 4;

    float acc[4][8];
    #pragma unroll
    for (int i = 0; i < 4; i++)
        #pragma unroll
        for (int j = 0; j < 8; j++) acc[i][j] = 0.f;

    for (int k0 = 0; k0 < FO; k0 += 32) {
        #pragma unroll
        for (int i = 0; i < 8; i++) {           // 64x32 A tile
            int l = tid + i * 256;
            int r = l >> 5, k = l & 31;
            As[l] = g_pz[(size_t)(row0 + r) * FO + k0 + k];
        }
        #pragma unroll
        for (int i = 0; i < 16; i++) {          // 32x128 B tile
            int l = tid + i * 256;
            int k = l >> 7, n = l & 127;
            int gn = n0 + n;
            Bs[l] = (gn < FIN) ? W2[(size_t)(k0 + k) * FIN + gn] : 0.f;
        }
        __syncthreads();
        #pragma unroll
        for (int k = 0; k < 32; k++) {
            float a[4];
            #pragma unroll
            for (int i = 0; i < 4; i++) a[i] = As[(ty * 4 + i) * 32 + k];
            float4 b0 = *reinterpret_cast<const float4*>(&Bs[k * 128 + tx * 8]);
            float4 b1 = *reinterpret_cast<const float4*>(&Bs[k * 128 + tx * 8 + 4]);
            float b[8] = {b0.x, b0.y, b0.z, b0.w, b1.x, b1.y, b1.z, b1.w};
            #pragma unroll
            for (int i = 0; i < 4; i++)
                #pragma unroll
                for (int j = 0; j < 8; j++)
                    acc[i][j] += a[i] * b[j];
        }
        __syncthreads();
    }
    #pragma unroll
    for (int i = 0; i < 4; i++) {
        int r = row0 + ty * 4 + i;
        #pragma unroll
        for (int j = 0; j < 8; j++) {
            int col = n0 + tx * 8 + j;
            if (col < FIN) outh[(size_t)r * FIN + col] = acc[i][j];
        }
    }
}

// ---------------------------------------------------------------------------
// readout: gv = (mask@emb)/rowsum ; g = sigmoid(gv / max(||gv||,1e-12)).
// ---------------------------------------------------------------------------
__global__ void readout_kernel(const float* __restrict__ emb, const float* __restrict__ emb_a)
{
    int row = blockIdx.x, t = threadIdx.x;
    __shared__ int   sidx[CAP];
    __shared__ float red[64];
    int cnt = g_gn_cnt[row];
    for (int k = t; k < cnt; k += 64) sidx[k] = g_gn_idx[(size_t)row * CAP + k];
    __syncthreads();
    float acc = 0.f, acca = 0.f;
    for (int k = 0; k < cnt; k++) {
        int j = sidx[k];
        acc  += emb[(size_t)j * FO + t];
        acca += emb_a[(size_t)j * FO + t];
    }
    float inv = 1.f / (float)cnt;
    float gv = acc * inv, gva = acca * inv;

    red[t] = gv * gv; __syncthreads();
    for (int s = 32; s >= 1; s >>= 1) { if (t < s) red[t] += red[t + s]; __syncthreads(); }
    float n1 = sqrtf(red[0]); __syncthreads();

    red[t] = gva * gva; __syncthreads();
    for (int s = 32; s >= 1; s >>= 1) { if (t < s) red[t] += red[t + s]; __syncthreads(); }
    float n2 = sqrtf(red[0]);

    float x1 = gv  / fmaxf(n1, 1e-12f);
    float x2 = gva / fmaxf(n2, 1e-12f);
    g_gv[(size_t)row * FO + t]  = 1.f / (1.f + expf(-x1));
    g_gva[(size_t)row * FO + t] = 1.f / (1.f + expf(-x2));
}

// ---------------------------------------------------------------------------
// Bilinear discriminator. v = emb^T W (thread e -> column e; coalesced W reads)
// ret[n]   = [ (emb^T W)·g   , (emb_a^T W)·g   ] + b
// ret_a[n] = [ (emb_a^T W)·ga, (emb^T W)·ga    ] + b
// ---------------------------------------------------------------------------
__global__ void disc_kernel(const float* __restrict__ emb, const float* __restrict__ emb_a,
                            const float* __restrict__ W, const float* __restrict__ bptr,
                            float* __restrict__ ret, float* __restrict__ ret_a)
{
    int row = blockIdx.x, e = threadIdx.x;
    __shared__ float se[64], sea[64], sg[64], sga[64];
    __shared__ float red[4 * 64];
    se[e]  = emb[(size_t)row * FO + e];
    sea[e] = emb_a[(size_t)row * FO + e];
    sg[e]  = g_gv[(size_t)row * FO + e];
    sga[e] = g_gva[(size_t)row * FO + e];
    __syncthreads();

    float v = 0.f, va = 0.f;
    #pragma unroll 8
    for (int d = 0; d < 64; d++) {
        float w = W[d * 64 + e];
        v  += se[d]  * w;
        va += sea[d] * w;
    }
    red[e]       = v  * sg[e];
    red[64 + e]  = va * sg[e];
    red[128 + e] = va * sga[e];
    red[192 + e] = v  * sga[e];
    __syncthreads();
    for (int s = 32; s >= 1; s >>= 1) {
        if (e < s) {
            red[e]       += red[e + s];
            red[64 + e]  += red[64 + e + s];
            red[128 + e] += red[128 + e + s];
            red[192 + e] += red[192 + e + s];
        }
        __syncthreads();
    }
    if (e == 0) {
        float b = bptr[0];
        ret[row * 2 + 0]   = red[0]   + b;
        ret[row * 2 + 1]   = red[64]  + b;
        ret_a[row * 2 + 0] = red[128] + b;
        ret_a[row * 2 + 1] = red[192] + b;
    }
}

// ---------------------------------------------------------------------------
extern "C" void kernel_launch(void* const* d_in, const int* in_sizes, int n_in,
                              void* d_out, int out_size)
{
    const float* feat   = (const float*)d_in[0];
    const float* feat_a = (const float*)d_in[1];
    const float* adj    = (const float*)d_in[2];
    const float* gn     = (const float*)d_in[3];
    const float* W1     = (const float*)d_in[4];
    const float* W2     = (const float*)d_in[5];
    const float* dW     = (const float*)d_in[6];
    const float* db     = (const float*)d_in[7];
    (void)in_sizes; (void)n_in; (void)out_size;

    float* out       = (float*)d_out;
    float* out_z     = out;                       // [8192,64]
    float* out_h     = out + 524288;              // [8192,3000]
    float* out_ret   = out + 25100288;            // [8192,2]
    float* out_ret_a = out + 25116672;            // [8192,2]
    float* out_emb   = out + 25133056;            // [8192,64]
    float* out_emb_a = out + 25657344;            // [8192,64]

    build_list_kernel<<<NN, 256>>>(adj, 0);
    build_list_kernel<<<NN, 256>>>(gn, 1);
    gemm_feat_kernel<<<dim3(NN / 128, 1, 2), 256>>>(feat, feat_a, W1);
    spmm1_kernel<<<NN, 64>>>(out_z, out_emb, out_emb_a);
    spmm2_kernel<<<NN, 64>>>(out_z);
    gemm_h_kernel<<<dim3(NN / 64, (FIN + 127) / 128), 256>>>(W2, out_h);
    readout_kernel<<<NN, 64>>>(out_emb, out_emb_a);
    disc_kernel<<<NN, 64>>>(out_emb, out_emb_a, dW, db, out_ret, out_ret_a);
}

// round 2
// speedup vs baseline: 1.1785x; 1.1785x over previous
#include <cuda_runtime.h>
#include <math.h>

#define NN 8192
#define FIN 3000
#define FO 64
#define CAP 192
#define KT 94            // ceil(3000/32)

// ---------------- scratch ----------------
__device__ int   g_adj_idx[NN * CAP];
__device__ int   g_adj_cnt[NN];
__device__ float g_dinv[NN];
__device__ int   g_gn_idx[NN * CAP];
__device__ int   g_gn_cnt[NN];
__device__ float g_xw1[NN * FO];
__device__ float g_xaw1[NN * FO];
__device__ float g_pz[NN * FO];
__device__ float g_gv[NN * FO];
__device__ float g_gva[NN * FO];

typedef unsigned long long u64;

__device__ __forceinline__ u64 dup2(float a) {
    u64 r; asm("mov.b64 %0, {%1, %1};" : "=l"(r) : "f"(a)); return r;
}
__device__ __forceinline__ void ffma2(u64& d, u64 a, u64 b) {
    asm("fma.rn.f32x2 %0, %1, %2, %0;" : "+l"(d) : "l"(a), "l"(b));
}
__device__ __forceinline__ float2 unp(u64 v) {
    float2 r; asm("mov.b64 {%0, %1}, %2;" : "=f"(r.x), "=f"(r.y) : "l"(v)); return r;
}
__device__ __forceinline__ void cp16(float* ds, const float* src, int sz) {
    unsigned d = (unsigned)__cvta_generic_to_shared(ds);
    asm volatile("cp.async.cg.shared.global [%0], [%1], 16, %2;" :: "r"(d), "l"(src), "r"(sz));
}
__device__ __forceinline__ void cpcommit() { asm volatile("cp.async.commit_group;"); }

// ---------------------------------------------------------------------------
// Fused: blocks [0,128) compute feat@W1 / feat_a@W1 with f32x2 FMA;
// blocks [128, 128+2*NN) scan adj / graph_neigh into ELL lists.
// The DRAM-bound builds overlap the compute-bound GEMM on the same grid.
// ---------------------------------------------------------------------------
__global__ void __launch_bounds__(128) fused_build_gemm(
    const float* __restrict__ feat, const float* __restrict__ feat_a,
    const float* __restrict__ W1,
    const float* __restrict__ adj, const float* __restrict__ gnm)
{
    __shared__ float As[128 * 33];     // stride 33: conflict-free loads & stores
    __shared__ float Bs[2 * 32 * 64];  // double buffered (cp.async)
    __shared__ int   counts[129];      // build-role scan

    int t  = threadIdx.x;
    int bx = blockIdx.x;

    if (bx < 128) {
        // ------------------------- GEMM role -------------------------
        int which = bx >> 6;
        int rb    = bx & 63;
        const float* A = which ? feat_a : feat;
        float*       C = which ? g_xaw1 : g_xw1;
        int row0 = rb * 128;
        int tx = t & 7, ty = t >> 3;

        u64 acc[8][4];
        #pragma unroll
        for (int i = 0; i < 8; i++)
            #pragma unroll
            for (int j = 0; j < 4; j++) acc[i][j] = 0ull;

        float4 areg[8];

        // prologue: tile 0
        {
            int k0 = 0;
            #pragma unroll
            for (int i = 0; i < 8; i++) {
                int lin = t + i * 128;
                int r = lin >> 3, kq = lin & 7;
                int gk = k0 + kq * 4;
                areg[i] = (gk + 4 <= FIN) ? *(const float4*)(A + (size_t)(row0 + r) * FIN + gk)
                                          : make_float4(0.f, 0.f, 0.f, 0.f);
            }
            #pragma unroll
            for (int i = 0; i < 4; i++) {
                int lin = t + i * 128;
                int k = lin >> 4, nq = lin & 15;
                cp16(&Bs[k * 64 + nq * 4], W1 + (size_t)(k0 + k) * FO + nq * 4,
                     (k0 + k < FIN) ? 16 : 0);
            }
            cpcommit();
            #pragma unroll
            for (int i = 0; i < 8; i++) {
                int lin = t + i * 128;
                int r = lin >> 3, kq = lin & 7;
                float* p = &As[r * 33 + kq * 4];
                p[0] = areg[i].x; p[1] = areg[i].y; p[2] = areg[i].z; p[3] = areg[i].w;
            }
        }

        int abase[8];
        #pragma unroll
        for (int i = 0; i < 8; i++) abase[i] = (ty * 8 + i) * 33;

        for (int kt = 0; kt < KT; kt++) {
            int buf = kt & 1;
            if (kt + 1 < KT) {
                int k0 = (kt + 1) * 32;
                #pragma unroll
                for (int i = 0; i < 8; i++) {
                    int lin = t + i * 128;
                    int r = lin >> 3, kq = lin & 7;
                    int gk = k0 + kq * 4;
                    areg[i] = (gk + 4 <= FIN) ? *(const float4*)(A + (size_t)(row0 + r) * FIN + gk)
                                              : make_float4(0.f, 0.f, 0.f, 0.f);
                }
                #pragma unroll
                for (int i = 0; i < 4; i++) {
                    int lin = t + i * 128;
                    int k = lin >> 4, nq = lin & 15;
                    cp16(&Bs[(buf ^ 1) * 2048 + k * 64 + nq * 4],
                         W1 + (size_t)(k0 + k) * FO + nq * 4, (k0 + k < FIN) ? 16 : 0);
                }
                cpcommit();
                asm volatile("cp.async.wait_group 1;");
            } else {
                asm volatile("cp.async.wait_group 0;");
            }
            __syncthreads();

            const float* bs = &Bs[buf * 2048];
            #pragma unroll 4
            for (int k = 0; k < 32; k++) {
                ulonglong2 q0 = *(const ulonglong2*)(bs + k * 64 + tx * 8);
                ulonglong2 q1 = *(const ulonglong2*)(bs + k * 64 + tx * 8 + 4);
                #pragma unroll
                for (int i = 0; i < 8; i++) {
                    u64 ad = dup2(As[abase[i] + k]);
                    ffma2(acc[i][0], ad, q0.x);
                    ffma2(acc[i][1], ad, q0.y);
                    ffma2(acc[i][2], ad, q1.x);
                    ffma2(acc[i][3], ad, q1.y);
                }
            }
            __syncthreads();
            if (kt + 1 < KT) {
                #pragma unroll
                for (int i = 0; i < 8; i++) {
                    int lin = t + i * 128;
                    int r = lin >> 3, kq = lin & 7;
                    float* p = &As[r * 33 + kq * 4];
                    p[0] = areg[i].x; p[1] = areg[i].y; p[2] = areg[i].z; p[3] = areg[i].w;
                }
            }
        }

        #pragma unroll
        for (int i = 0; i < 8; i++) {
            float2 a0 = unp(acc[i][0]), a1 = unp(acc[i][1]);
            float2 a2 = unp(acc[i][2]), a3 = unp(acc[i][3]);
            size_t r = row0 + ty * 8 + i;
            *(float4*)(C + r * FO + tx * 8)     = make_float4(a0.x, a0.y, a1.x, a1.y);
            *(float4*)(C + r * FO + tx * 8 + 4) = make_float4(a2.x, a2.y, a3.x, a3.y);
        }
    } else {
        // ------------------------- BUILD role -------------------------
        int bxx   = bx - 128;
        int which = bxx >> 13;           // 0: adj, 1: graph_neigh
        int row   = bxx & (NN - 1);
        const float* mat = which ? gnm : adj;
        const float4* rp = (const float4*)(mat + (size_t)row * NN);
        int base = t * 16;               // 16 float4 = 64 cols / thread

        int c = 0;
        #pragma unroll
        for (int q = 0; q < 16; q++) {
            float4 v = rp[base + q];
            c += (v.x != 0.f) + (v.y != 0.f) + (v.z != 0.f) + (v.w != 0.f);
        }
        counts[t] = c;
        __syncthreads();
        if (t == 0) {
            int s = 0;
            for (int i = 0; i < 128; i++) { int cc = counts[i]; counts[i] = s; s += cc; }
            counts[128] = s;
        }
        __syncthreads();

        int o = counts[t];
        int* outl = (which ? g_gn_idx : g_adj_idx) + (size_t)row * CAP;
        #pragma unroll
        for (int q = 0; q < 16; q++) {
            float4 v = rp[base + q];     // re-read: L1 hit
            int j0 = (base + q) * 4;
            if (v.x != 0.f && o < CAP) outl[o++] = j0;
            if (v.y != 0.f && o < CAP) outl[o++] = j0 + 1;
            if (v.z != 0.f && o < CAP) outl[o++] = j0 + 2;
            if (v.w != 0.f && o < CAP) outl[o++] = j0 + 3;
        }
        if (t == 0) {
            int tot = counts[128];
            if (which == 0) {
                if (tot < CAP) { outl[tot] = row; tot++; }   // self loop
                g_adj_cnt[row] = tot;
                g_dinv[row]    = rsqrtf((float)tot);
            } else {
                g_gn_cnt[row] = tot;
            }
        }
    }
}

// ---------------------------------------------------------------------------
// z = P @ XW1 ; emb = relu(z) ; emb_a = relu(P @ XaW1).   (2-way unrolled)
// ---------------------------------------------------------------------------
__global__ void spmm1_kernel(float* __restrict__ out_z, float* __restrict__ out_emb,
                             float* __restrict__ out_emb_a)
{
    int row = blockIdx.x, t = threadIdx.x;
    __shared__ int   sidx[CAP];
    __shared__ float sw[CAP];
    int cnt = g_adj_cnt[row];
    for (int k = t; k < cnt; k += 64) {
        int j = g_adj_idx[row * CAP + k];
        sidx[k] = j * 64 + t - t;  // store base row index
        sidx[k] = j;
        sw[k]   = g_dinv[j];
    }
    __syncthreads();
    float a0 = 0.f, a1 = 0.f, b0 = 0.f, b1 = 0.f;
    int k = 0;
    for (; k + 2 <= cnt; k += 2) {
        int j0 = sidx[k] * 64 + t, j1 = sidx[k + 1] * 64 + t;
        float w0 = sw[k], w1 = sw[k + 1];
        a0 += w0 * g_xw1[j0];  b0 += w0 * g_xaw1[j0];
        a1 += w1 * g_xw1[j1];  b1 += w1 * g_xaw1[j1];
    }
    if (k < cnt) {
        int j = sidx[k] * 64 + t; float w = sw[k];
        a0 += w * g_xw1[j];  b0 += w * g_xaw1[j];
    }
    float di = g_dinv[row];
    float z = di * (a0 + a1), za = di * (b0 + b1);
    out_z[row * 64 + t]     = z;
    out_emb[row * 64 + t]   = fmaxf(z, 0.f);
    out_emb_a[row * 64 + t] = fmaxf(za, 0.f);
}

// ---------------------------------------------------------------------------
// Fused: Pz = P @ z  AND  readout (both depend only on spmm1 outputs).
// ---------------------------------------------------------------------------
__global__ void spmm2_readout_kernel(const float* __restrict__ z,
                                     const float* __restrict__ emb,
                                     const float* __restrict__ emb_a)
{
    int row = blockIdx.x, t = threadIdx.x;
    __shared__ int   sidx[CAP];
    __shared__ float sw[CAP];
    __shared__ float red[64];

    // --- spmm2 ---
    int cnt = g_adj_cnt[row];
    for (int k = t; k < cnt; k += 64) {
        int j = g_adj_idx[row * CAP + k];
        sidx[k] = j;
        sw[k]   = g_dinv[j];
    }
    __syncthreads();
    float p0 = 0.f, p1 = 0.f;
    int k = 0;
    for (; k + 2 <= cnt; k += 2) {
        p0 += sw[k]     * z[sidx[k]     * 64 + t];
        p1 += sw[k + 1] * z[sidx[k + 1] * 64 + t];
    }
    if (k < cnt) p0 += sw[k] * z[sidx[k] * 64 + t];
    g_pz[row * 64 + t] = g_dinv[row] * (p0 + p1);

    // --- readout ---
    int gcnt = g_gn_cnt[row];
    __syncthreads();
    for (int kk = t; kk < gcnt; kk += 64) sidx[kk] = g_gn_idx[row * CAP + kk];
    __syncthreads();
    float s0 = 0.f, s1 = 0.f, sa0 = 0.f, sa1 = 0.f;
    k = 0;
    for (; k + 2 <= gcnt; k += 2) {
        int j0 = sidx[k] * 64 + t, j1 = sidx[k + 1] * 64 + t;
        s0 += emb[j0];   s1 += emb[j1];
        sa0 += emb_a[j0]; sa1 += emb_a[j1];
    }
    if (k < gcnt) { int j = sidx[k] * 64 + t; s0 += emb[j]; sa0 += emb_a[j]; }
    float inv = 1.f / (float)gcnt;
    float gv = (s0 + s1) * inv, gva = (sa0 + sa1) * inv;

    red[t] = gv * gv; __syncthreads();
    for (int s = 32; s >= 1; s >>= 1) { if (t < s) red[t] += red[t + s]; __syncthreads(); }
    float n1 = sqrtf(red[0]); __syncthreads();
    red[t] = gva * gva; __syncthreads();
    for (int s = 32; s >= 1; s >>= 1) { if (t < s) red[t] += red[t + s]; __syncthreads(); }
    float n2 = sqrtf(red[0]);

    float x1 = gv  / fmaxf(n1, 1e-12f);
    float x2 = gva / fmaxf(n2, 1e-12f);
    g_gv[row * 64 + t]  = 1.f / (1.f + expf(-x1));
    g_gva[row * 64 + t] = 1.f / (1.f + expf(-x2));
}

// ---------------------------------------------------------------------------
// h = Pz @ W2. M=8192 K=64 N=3000. 64x64 tile, 128 thr, 4x8/thread, f32x2.
// ---------------------------------------------------------------------------
__global__ void __launch_bounds__(128) gemm_h_kernel(const float* __restrict__ W2,
                                                     float* __restrict__ outh)
{
    __shared__ float As[64 * 65];
    __shared__ float Bs[64 * 64];
    int t = threadIdx.x;
    int row0 = blockIdx.x * 64;
    int n0   = blockIdx.y * 64;
    int tx = t & 7, ty = t >> 3;

    #pragma unroll
    for (int i = 0; i < 8; i++) {
        int lin = t + i * 128;
        int r = lin >> 4, kq = lin & 15;
        float4 v = *(const float4*)(g_pz + (size_t)(row0 + r) * 64 + kq * 4);
        float* p = &As[r * 65 + kq * 4];
        p[0] = v.x; p[1] = v.y; p[2] = v.z; p[3] = v.w;
    }
    #pragma unroll
    for (int i = 0; i < 8; i++) {
        int lin = t + i * 128;
        int k = lin >> 4, nq = lin & 15;
        int col = n0 + nq * 4;
        float4 v = (col < FIN) ? *(const float4*)(W2 + (size_t)k * FIN + col)
                               : make_float4(0.f, 0.f, 0.f, 0.f);
        *(float4*)(&Bs[k * 64 + nq * 4]) = v;
    }
    __syncthreads();

    u64 acc[4][4];
    #pragma unroll
    for (int i = 0; i < 4; i++)
        #pragma unroll
        for (int j = 0; j < 4; j++) acc[i][j] = 0ull;

    int abase[4];
    #pragma unroll
    for (int i = 0; i < 4; i++) abase[i] = (ty * 4 + i) * 65;

    #pragma unroll 8
    for (int k = 0; k < 64; k++) {
        ulonglong2 q0 = *(const ulonglong2*)(&Bs[k * 64 + tx * 8]);
        ulonglong2 q1 = *(const ulonglong2*)(&Bs[k * 64 + tx * 8 + 4]);
        #pragma unroll
        for (int i = 0; i < 4; i++) {
            u64 ad = dup2(As[abase[i] + k]);
            ffma2(acc[i][0], ad, q0.x);
            ffma2(acc[i][1], ad, q0.y);
            ffma2(acc[i][2], ad, q1.x);
            ffma2(acc[i][3], ad, q1.y);
        }
    }

    int cb = n0 + tx * 8;
    if (cb < FIN) {
        #pragma unroll
        for (int i = 0; i < 4; i++) {
            float2 a0 = unp(acc[i][0]), a1 = unp(acc[i][1]);
            float2 a2 = unp(acc[i][2]), a3 = unp(acc[i][3]);
            size_t r = row0 + ty * 4 + i;
            *(float4*)(outh + r * FIN + cb)     = make_float4(a0.x, a0.y, a1.x, a1.y);
            *(float4*)(outh + r * FIN + cb + 4) = make_float4(a2.x, a2.y, a3.x, a3.y);
        }
    }
}

// ---------------------------------------------------------------------------
// Bilinear discriminator.
// ---------------------------------------------------------------------------
__global__ void disc_kernel(const float* __restrict__ emb, const float* __restrict__ emb_a,
                            const float* __restrict__ W, const float* __restrict__ bptr,
                            float* __restrict__ ret, float* __restrict__ ret_a)
{
    int row = blockIdx.x, e = threadIdx.x;
    __shared__ float se[64], sea[64], sg[64], sga[64];
    __shared__ float red[4 * 64];
    se[e]  = emb[row * 64 + e];
    sea[e] = emb_a[row * 64 + e];
    sg[e]  = g_gv[row * 64 + e];
    sga[e] = g_gva[row * 64 + e];
    __syncthreads();

    float v = 0.f, va = 0.f;
    #pragma unroll 8
    for (int d = 0; d < 64; d++) {
        float w = W[d * 64 + e];
        v  += se[d]  * w;
        va += sea[d] * w;
    }
    red[e]       = v  * sg[e];
    red[64 + e]  = va * sg[e];
    red[128 + e] = va * sga[e];
    red[192 + e] = v  * sga[e];
    __syncthreads();
    for (int s = 32; s >= 1; s >>= 1) {
        if (e < s) {
            red[e]       += red[e + s];
            red[64 + e]  += red[64 + e + s];
            red[128 + e] += red[128 + e + s];
            red[192 + e] += red[192 + e + s];
        }
        __syncthreads();
    }
    if (e == 0) {
        float b = bptr[0];
        ret[row * 2 + 0]   = red[0]   + b;
        ret[row * 2 + 1]   = red[64]  + b;
        ret_a[row * 2 + 0] = red[128] + b;
        ret_a[row * 2 + 1] = red[192] + b;
    }
}

// ---------------------------------------------------------------------------
extern "C" void kernel_launch(void* const* d_in, const int* in_sizes, int n_in,
                              void* d_out, int out_size)
{
    const float* feat   = (const float*)d_in[0];
    const float* feat_a = (const float*)d_in[1];
    const float* adj    = (const float*)d_in[2];
    const float* gnm    = (const float*)d_in[3];
    const float* W1     = (const float*)d_in[4];
    const float* W2     = (const float*)d_in[5];
    const float* dW     = (const float*)d_in[6];
    const float* db     = (const float*)d_in[7];
    (void)in_sizes; (void)n_in; (void)out_size;

    float* out       = (float*)d_out;
    float* out_z     = out;                       // [8192,64]
    float* out_h     = out + 524288;              // [8192,3000]
    float* out_ret   = out + 25100288;            // [8192,2]
    float* out_ret_a = out + 25116672;            // [8192,2]
    float* out_emb   = out + 25133056;            // [8192,64]
    float* out_emb_a = out + 25657344;            // [8192,64]

    fused_build_gemm<<<128 + 2 * NN, 128>>>(feat, feat_a, W1, adj, gnm);
    spmm1_kernel<<<NN, 64>>>(out_z, out_emb, out_emb_a);
    spmm2_readout_kernel<<<NN, 64>>>(out_z, out_emb, out_emb_a);
    gemm_h_kernel<<<dim3(NN / 64, (FIN + 63) / 64), 128>>>(W2, out_h);
    disc_kernel<<<NN, 64>>>(out_emb, out_emb_a, dW, db, out_ret, out_ret_a);
}

// round 3
// speedup vs baseline: 1.2780x; 1.0844x over previous
#include <cuda_runtime.h>
#include <math.h>

#define NN 8192
#define FIN 3000
#define FO 64
#define CAP 192
#define KT 94            // ceil(3000/32)

// ---------------- scratch ----------------
__device__ int   g_adj_idx[NN * CAP];
__device__ int   g_adj_cnt[NN];
__device__ float g_dinv[NN];
__device__ int   g_gn_idx[NN * CAP];
__device__ int   g_gn_cnt[NN];
__device__ float g_xw1[NN * FO];
__device__ float g_xaw1[NN * FO];
__device__ float g_pz[NN * FO];

typedef unsigned long long u64;

__device__ __forceinline__ u64 dup2(float a) {
    u64 r; asm("mov.b64 %0, {%1, %1};" : "=l"(r) : "f"(a)); return r;
}
__device__ __forceinline__ void ffma2(u64& d, u64 a, u64 b) {
    asm("fma.rn.f32x2 %0, %1, %2, %0;" : "+l"(d) : "l"(a), "l"(b));
}
__device__ __forceinline__ float2 unp(u64 v) {
    float2 r; asm("mov.b64 {%0, %1}, %2;" : "=f"(r.x), "=f"(r.y) : "l"(v)); return r;
}
__device__ __forceinline__ void cp16(float* ds, const float* src, int sz) {
    unsigned d = (unsigned)__cvta_generic_to_shared(ds);
    asm volatile("cp.async.cg.shared.global [%0], [%1], 16, %2;" :: "r"(d), "l"(src), "r"(sz));
}
__device__ __forceinline__ void cpcommit() { asm volatile("cp.async.commit_group;"); }

// ---------------------------------------------------------------------------
// Fused: blocks [0,128) compute feat@W1 / feat_a@W1 (f32x2 FMA);
// blocks [128, 128+2*NN) scan adj / graph_neigh into ELL lists.
// ---------------------------------------------------------------------------
__global__ void __launch_bounds__(128) fused_build_gemm(
    const float* __restrict__ feat, const float* __restrict__ feat_a,
    const float* __restrict__ W1,
    const float* __restrict__ adj, const float* __restrict__ gnm)
{
    __shared__ float As[128 * 33];     // 8*33 % 32 = 8 -> conflict-free bcast reads
    __shared__ float Bs[2 * 32 * 64];  // double buffered (cp.async)
    __shared__ int   counts[129];

    int t  = threadIdx.x;
    int bx = blockIdx.x;

    if (bx < 128) {
        // ------------------------- GEMM role -------------------------
        int which = bx >> 6;
        int rb    = bx & 63;
        const float* A = which ? feat_a : feat;
        float*       C = which ? g_xaw1 : g_xw1;
        int row0 = rb * 128;
        int tx = t & 7, ty = t >> 3;

        u64 acc[8][4];
        #pragma unroll
        for (int i = 0; i < 8; i++)
            #pragma unroll
            for (int j = 0; j < 4; j++) acc[i][j] = 0ull;

        float4 areg[8];

        {   // prologue: tile 0
            #pragma unroll
            for (int i = 0; i < 8; i++) {
                int lin = t + i * 128;
                int r = lin >> 3, kq = lin & 7;
                int gk = kq * 4;
                areg[i] = *(const float4*)(A + (size_t)(row0 + r) * FIN + gk);
            }
            #pragma unroll
            for (int i = 0; i < 4; i++) {
                int lin = t + i * 128;
                int k = lin >> 4, nq = lin & 15;
                cp16(&Bs[k * 64 + nq * 4], W1 + (size_t)k * FO + nq * 4, 16);
            }
            cpcommit();
            #pragma unroll
            for (int i = 0; i < 8; i++) {
                int lin = t + i * 128;
                int r = lin >> 3, kq = lin & 7;
                float* p = &As[r * 33 + kq * 4];
                p[0] = areg[i].x; p[1] = areg[i].y; p[2] = areg[i].z; p[3] = areg[i].w;
            }
        }

        int abase[8];
        #pragma unroll
        for (int i = 0; i < 8; i++) abase[i] = (ty * 8 + i) * 33;

        for (int kt = 0; kt < KT; kt++) {
            int buf = kt & 1;
            if (kt + 1 < KT) {
                int k0 = (kt + 1) * 32;
                #pragma unroll
                for (int i = 0; i < 8; i++) {
                    int lin = t + i * 128;
                    int r = lin >> 3, kq = lin & 7;
                    int gk = k0 + kq * 4;
                    areg[i] = (gk + 4 <= FIN) ? *(const float4*)(A + (size_t)(row0 + r) * FIN + gk)
                                              : make_float4(0.f, 0.f, 0.f, 0.f);
                }
                #pragma unroll
                for (int i = 0; i < 4; i++) {
                    int lin = t + i * 128;
                    int k = lin >> 4, nq = lin & 15;
                    cp16(&Bs[(buf ^ 1) * 2048 + k * 64 + nq * 4],
                         W1 + (size_t)(k0 + k) * FO + nq * 4, (k0 + k < FIN) ? 16 : 0);
                }
                cpcommit();
                asm volatile("cp.async.wait_group 1;");
            } else {
                asm volatile("cp.async.wait_group 0;");
            }
            __syncthreads();

            const float* bs = &Bs[buf * 2048];
            #pragma unroll 4
            for (int k = 0; k < 32; k++) {
                ulonglong2 q0 = *(const ulonglong2*)(bs + k * 64 + tx * 8);
                ulonglong2 q1 = *(const ulonglong2*)(bs + k * 64 + tx * 8 + 4);
                #pragma unroll
                for (int i = 0; i < 8; i++) {
                    u64 ad = dup2(As[abase[i] + k]);
                    ffma2(acc[i][0], ad, q0.x);
                    ffma2(acc[i][1], ad, q0.y);
                    ffma2(acc[i][2], ad, q1.x);
                    ffma2(acc[i][3], ad, q1.y);
                }
            }
            __syncthreads();
            if (kt + 1 < KT) {
                #pragma unroll
                for (int i = 0; i < 8; i++) {
                    int lin = t + i * 128;
                    int r = lin >> 3, kq = lin & 7;
                    float* p = &As[r * 33 + kq * 4];
                    p[0] = areg[i].x; p[1] = areg[i].y; p[2] = areg[i].z; p[3] = areg[i].w;
                }
            }
        }

        #pragma unroll
        for (int i = 0; i < 8; i++) {
            float2 a0 = unp(acc[i][0]), a1 = unp(acc[i][1]);
            float2 a2 = unp(acc[i][2]), a3 = unp(acc[i][3]);
            size_t r = row0 + ty * 8 + i;
            *(float4*)(C + r * FO + tx * 8)     = make_float4(a0.x, a0.y, a1.x, a1.y);
            *(float4*)(C + r * FO + tx * 8 + 4) = make_float4(a2.x, a2.y, a3.x, a3.y);
        }
    } else {
        // ------------------------- BUILD role -------------------------
        int bxx   = bx - 128;
        int which = bxx >> 13;
        int row   = bxx & (NN - 1);
        const float* mat = which ? gnm : adj;
        const float4* rp = (const float4*)(mat + (size_t)row * NN);
        int base = t * 16;

        int c = 0;
        #pragma unroll
        for (int q = 0; q < 16; q++) {
            float4 v = rp[base + q];
            c += (v.x != 0.f) + (v.y != 0.f) + (v.z != 0.f) + (v.w != 0.f);
        }
        counts[t] = c;
        __syncthreads();
        if (t == 0) {
            int s = 0;
            for (int i = 0; i < 128; i++) { int cc = counts[i]; counts[i] = s; s += cc; }
            counts[128] = s;
        }
        __syncthreads();

        int o = counts[t];
        int* outl = (which ? g_gn_idx : g_adj_idx) + (size_t)row * CAP;
        #pragma unroll
        for (int q = 0; q < 16; q++) {
            float4 v = rp[base + q];
            int j0 = (base + q) * 4;
            if (v.x != 0.f && o < CAP) outl[o++] = j0;
            if (v.y != 0.f && o < CAP) outl[o++] = j0 + 1;
            if (v.z != 0.f && o < CAP) outl[o++] = j0 + 2;
            if (v.w != 0.f && o < CAP) outl[o++] = j0 + 3;
        }
        if (t == 0) {
            int tot = counts[128];
            if (which == 0) {
                if (tot < CAP) { outl[tot] = row; tot++; }
                g_adj_cnt[row] = tot;
                g_dinv[row]    = rsqrtf((float)tot);
            } else {
                g_gn_cnt[row] = tot;
            }
        }
    }
}

// ---------------------------------------------------------------------------
// z = P@XW1 ; emb = relu(z) ; emb_a = relu(P@XaW1).  2 rows/block, unroll-4.
// ---------------------------------------------------------------------------
__global__ void __launch_bounds__(128) spmm1_kernel(
    float* __restrict__ out_z, float* __restrict__ out_emb, float* __restrict__ out_emb_a)
{
    int t = threadIdx.x, h = t >> 6, tt = t & 63;
    int row = blockIdx.x * 2 + h;
    __shared__ int   sidx[2][CAP];
    __shared__ float sw[2][CAP];
    int cnt = g_adj_cnt[row];
    for (int k = tt; k < cnt; k += 64) {
        int j = g_adj_idx[row * CAP + k];
        sidx[h][k] = j * 64;
        sw[h][k]   = g_dinv[j];
    }
    __syncthreads();
    float a0 = 0.f, a1 = 0.f, a2 = 0.f, a3 = 0.f;
    float b0 = 0.f, b1 = 0.f, b2 = 0.f, b3 = 0.f;
    int k = 0;
    for (; k + 4 <= cnt; k += 4) {
        int j0 = sidx[h][k] + tt,     j1 = sidx[h][k + 1] + tt;
        int j2 = sidx[h][k + 2] + tt, j3 = sidx[h][k + 3] + tt;
        float w0 = sw[h][k], w1 = sw[h][k + 1], w2 = sw[h][k + 2], w3 = sw[h][k + 3];
        a0 += w0 * g_xw1[j0];  b0 += w0 * g_xaw1[j0];
        a1 += w1 * g_xw1[j1];  b1 += w1 * g_xaw1[j1];
        a2 += w2 * g_xw1[j2];  b2 += w2 * g_xaw1[j2];
        a3 += w3 * g_xw1[j3];  b3 += w3 * g_xaw1[j3];
    }
    for (; k < cnt; k++) {
        int j = sidx[h][k] + tt; float w = sw[h][k];
        a0 += w * g_xw1[j];  b0 += w * g_xaw1[j];
    }
    float di = g_dinv[row];
    float z  = di * ((a0 + a1) + (a2 + a3));
    float za = di * ((b0 + b1) + (b2 + b3));
    out_z[row * 64 + tt]     = z;
    out_emb[row * 64 + tt]   = fmaxf(z, 0.f);
    out_emb_a[row * 64 + tt] = fmaxf(za, 0.f);
}

// ---------------------------------------------------------------------------
// Fused: Pz = P@z ; readout (gv -> sigmoid) ; bilinear discriminator.
// All row-local given spmm1 outputs. 2 rows/block.
// ---------------------------------------------------------------------------
__global__ void __launch_bounds__(128) spmm2_readout_disc_kernel(
    const float* __restrict__ z, const float* __restrict__ emb,
    const float* __restrict__ emb_a, const float* __restrict__ W,
    const float* __restrict__ bptr,
    float* __restrict__ ret, float* __restrict__ ret_a)
{
    int t = threadIdx.x, h = t >> 6, tt = t & 63;
    int row = blockIdx.x * 2 + h;
    __shared__ int   sidx[2][CAP];
    __shared__ float sw[2][CAP];
    __shared__ float red[2][256];
    __shared__ float sg[2][64], sga[2][64], se[2][64], sea[2][64];

    // --- spmm2: Pz ---
    int cnt = g_adj_cnt[row];
    for (int k = tt; k < cnt; k += 64) {
        int j = g_adj_idx[row * CAP + k];
        sidx[h][k] = j * 64;
        sw[h][k]   = g_dinv[j];
    }
    __syncthreads();
    float p0 = 0.f, p1 = 0.f, p2 = 0.f, p3 = 0.f;
    int k = 0;
    for (; k + 4 <= cnt; k += 4) {
        p0 += sw[h][k]     * z[sidx[h][k]     + tt];
        p1 += sw[h][k + 1] * z[sidx[h][k + 1] + tt];
        p2 += sw[h][k + 2] * z[sidx[h][k + 2] + tt];
        p3 += sw[h][k + 3] * z[sidx[h][k + 3] + tt];
    }
    for (; k < cnt; k++) p0 += sw[h][k] * z[sidx[h][k] + tt];
    g_pz[row * 64 + tt] = g_dinv[row] * ((p0 + p1) + (p2 + p3));

    // --- readout ---
    int gcnt = g_gn_cnt[row];
    __syncthreads();
    for (int kk = tt; kk < gcnt; kk += 64) sidx[h][kk] = g_gn_idx[row * CAP + kk] * 64;
    __syncthreads();
    float s0 = 0.f, s1 = 0.f, s2 = 0.f, s3 = 0.f;
    float u0 = 0.f, u1 = 0.f, u2 = 0.f, u3 = 0.f;
    k = 0;
    for (; k + 4 <= gcnt; k += 4) {
        int j0 = sidx[h][k] + tt,     j1 = sidx[h][k + 1] + tt;
        int j2 = sidx[h][k + 2] + tt, j3 = sidx[h][k + 3] + tt;
        s0 += emb[j0];  u0 += emb_a[j0];
        s1 += emb[j1];  u1 += emb_a[j1];
        s2 += emb[j2];  u2 += emb_a[j2];
        s3 += emb[j3];  u3 += emb_a[j3];
    }
    for (; k < gcnt; k++) { int j = sidx[h][k] + tt; s0 += emb[j]; u0 += emb_a[j]; }
    float inv = 1.f / (float)gcnt;
    float gv  = ((s0 + s1) + (s2 + s3)) * inv;
    float gva = ((u0 + u1) + (u2 + u3)) * inv;

    red[h][tt] = gv * gv; __syncthreads();
    for (int s = 32; s >= 1; s >>= 1) { if (tt < s) red[h][tt] += red[h][tt + s]; __syncthreads(); }
    float n1 = sqrtf(red[h][0]); __syncthreads();
    red[h][tt] = gva * gva; __syncthreads();
    for (int s = 32; s >= 1; s >>= 1) { if (tt < s) red[h][tt] += red[h][tt + s]; __syncthreads(); }
    float n2 = sqrtf(red[h][0]);

    float x1 = gv  / fmaxf(n1, 1e-12f);
    float x2 = gva / fmaxf(n2, 1e-12f);
    sg[h][tt]  = 1.f / (1.f + expf(-x1));
    sga[h][tt] = 1.f / (1.f + expf(-x2));
    se[h][tt]  = emb[row * 64 + tt];
    sea[h][tt] = emb_a[row * 64 + tt];
    __syncthreads();

    // --- discriminator ---
    float v = 0.f, va = 0.f;
    #pragma unroll 8
    for (int d = 0; d < 64; d++) {
        float w = W[d * 64 + tt];
        v  += se[h][d]  * w;
        va += sea[h][d] * w;
    }
    red[h][tt]       = v  * sg[h][tt];
    red[h][64 + tt]  = va * sg[h][tt];
    red[h][128 + tt] = va * sga[h][tt];
    red[h][192 + tt] = v  * sga[h][tt];
    __syncthreads();
    for (int s = 32; s >= 1; s >>= 1) {
        if (tt < s) {
            red[h][tt]       += red[h][tt + s];
            red[h][64 + tt]  += red[h][64 + tt + s];
            red[h][128 + tt] += red[h][128 + tt + s];
            red[h][192 + tt] += red[h][192 + tt + s];
        }
        __syncthreads();
    }
    if (tt == 0) {
        float b = bptr[0];
        ret[row * 2 + 0]   = red[h][0]   + b;
        ret[row * 2 + 1]   = red[h][64]  + b;
        ret_a[row * 2 + 0] = red[h][128] + b;
        ret_a[row * 2 + 1] = red[h][192] + b;
    }
}

// ---------------------------------------------------------------------------
// h = Pz @ W2. M=8192 K=64 N=3000. 128x64 block tile, 128 thr, 8x8/thread.
// As stride 65: 8-row-spaced broadcast addrs hit distinct banks.
// ---------------------------------------------------------------------------
__global__ void __launch_bounds__(128) gemm_h_kernel(const float* __restrict__ W2,
                                                     float* __restrict__ outh)
{
    __shared__ float As[128 * 65];
    __shared__ float Bs[64 * 64];
    int t = threadIdx.x;
    int row0 = blockIdx.x * 128;
    int n0   = blockIdx.y * 64;
    int tx = t & 7, ty = t >> 3;

    #pragma unroll
    for (int i = 0; i < 16; i++) {           // 128x64 A tile (Pz)
        int lin = t + i * 128;
        int r = lin >> 4, kq = lin & 15;
        float4 v = *(const float4*)(g_pz + (size_t)(row0 + r) * 64 + kq * 4);
        float* p = &As[r * 65 + kq * 4];
        p[0] = v.x; p[1] = v.y; p[2] = v.z; p[3] = v.w;
    }
    #pragma unroll
    for (int i = 0; i < 8; i++) {            // 64x64 B tile (W2)
        int lin = t + i * 128;
        int kk = lin >> 4, nq = lin & 15;
        int col = n0 + nq * 4;
        float4 v = (col < FIN) ? *(const float4*)(W2 + (size_t)kk * FIN + col)
                               : make_float4(0.f, 0.f, 0.f, 0.f);
        *(float4*)(&Bs[kk * 64 + nq * 4]) = v;
    }
    __syncthreads();

    u64 acc[8][4];
    #pragma unroll
    for (int i = 0; i < 8; i++)
        #pragma unroll
        for (int j = 0; j < 4; j++) acc[i][j] = 0ull;

    int abase[8];
    #pragma unroll
    for (int i = 0; i < 8; i++) abase[i] = (ty * 8 + i) * 65;

    #pragma unroll 8
    for (int k = 0; k < 64; k++) {
        ulonglong2 q0 = *(const ulonglong2*)(&Bs[k * 64 + tx * 8]);
        ulonglong2 q1 = *(const ulonglong2*)(&Bs[k * 64 + tx * 8 + 4]);
        #pragma unroll
        for (int i = 0; i < 8; i++) {
            u64 ad = dup2(As[abase[i] + k]);
            ffma2(acc[i][0], ad, q0.x);
            ffma2(acc[i][1], ad, q0.y);
            ffma2(acc[i][2], ad, q1.x);
            ffma2(acc[i][3], ad, q1.y);
        }
    }

    int cb = n0 + tx * 8;
    if (cb < FIN) {
        #pragma unroll
        for (int i = 0; i < 8; i++) {
            float2 a0 = unp(acc[i][0]), a1 = unp(acc[i][1]);
            float2 a2 = unp(acc[i][2]), a3 = unp(acc[i][3]);
            size_t r = row0 + ty * 8 + i;
            *(float4*)(outh + r * FIN + cb)     = make_float4(a0.x, a0.y, a1.x, a1.y);
            *(float4*)(outh + r * FIN + cb + 4) = make_float4(a2.x, a2.y, a3.x, a3.y);
        }
    }
}

// ---------------------------------------------------------------------------
extern "C" void kernel_launch(void* const* d_in, const int* in_sizes, int n_in,
                              void* d_out, int out_size)
{
    const float* feat   = (const float*)d_in[0];
    const float* feat_a = (const float*)d_in[1];
    const float* adj    = (const float*)d_in[2];
    const float* gnm    = (const float*)d_in[3];
    const float* W1     = (const float*)d_in[4];
    const float* W2     = (const float*)d_in[5];
    const float* dW     = (const float*)d_in[6];
    const float* db     = (const float*)d_in[7];
    (void)in_sizes; (void)n_in; (void)out_size;

    float* out       = (float*)d_out;
    float* out_z     = out;                       // [8192,64]
    float* out_h     = out + 524288;              // [8192,3000]
    float* out_ret   = out + 25100288;            // [8192,2]
    float* out_ret_a = out + 25116672;            // [8192,2]
    float* out_emb   = out + 25133056;            // [8192,64]
    float* out_emb_a = out + 25657344;            // [8192,64]

    fused_build_gemm<<<128 + 2 * NN, 128>>>(feat, feat_a, W1, adj, gnm);
    spmm1_kernel<<<NN / 2, 128>>>(out_z, out_emb, out_emb_a);
    spmm2_readout_disc_kernel<<<NN / 2, 128>>>(out_z, out_emb, out_emb_a, dW, db,
                                               out_ret, out_ret_a);
    gemm_h_kernel<<<dim3(NN / 128, (FIN + 63) / 64), 128>>>(W2, out_h);
}

// round 4
// speedup vs baseline: 1.3951x; 1.0917x over previous
#include <cuda_runtime.h>
#include <math.h>

#define NN 8192
#define FIN 3000
#define FO 64
#define CAP 192
#define KT 94            // ceil(3000/32)

// ---------------- scratch ----------------
__device__ int   g_adj_idx[NN * CAP];
__device__ int   g_adj_cnt[NN];
__device__ float g_dinv[NN];
__device__ int   g_gn_idx[NN * CAP];
__device__ int   g_gn_cnt[NN];
__device__ float g_xw1[NN * FO];
__device__ float g_xaw1[NN * FO];
__device__ float g_pz[NN * FO];

typedef unsigned long long u64;

__device__ __forceinline__ u64 dup2(float a) {
    u64 r; asm("mov.b64 %0, {%1, %1};" : "=l"(r) : "f"(a)); return r;
}
__device__ __forceinline__ void ffma2(u64& d, u64 a, u64 b) {
    asm("fma.rn.f32x2 %0, %1, %2, %0;" : "+l"(d) : "l"(a), "l"(b));
}
__device__ __forceinline__ float2 unp(u64 v) {
    float2 r; asm("mov.b64 {%0, %1}, %2;" : "=f"(r.x), "=f"(r.y) : "l"(v)); return r;
}
__device__ __forceinline__ void cp16(float* ds, const float* src, int sz) {
    unsigned d = (unsigned)__cvta_generic_to_shared(ds);
    asm volatile("cp.async.cg.shared.global [%0], [%1], 16, %2;" :: "r"(d), "l"(src), "r"(sz));
}
__device__ __forceinline__ void cpcommit() { asm volatile("cp.async.commit_group;"); }

// ---------------------------------------------------------------------------
// Fused: blocks [0,128) compute feat@W1 / feat_a@W1 (f32x2 FMA);
// blocks [128, 128+2*NN) scan adj / graph_neigh into ELL lists.
// Build role: coalesced interleaved loads (lane-contiguous), one pass,
// 64-bit nonzero mask per thread, shfl warp scan. Deterministic fixed order.
// ---------------------------------------------------------------------------
__global__ void __launch_bounds__(128) fused_build_gemm(
    const float* __restrict__ feat, const float* __restrict__ feat_a,
    const float* __restrict__ W1,
    const float* __restrict__ adj, const float* __restrict__ gnm)
{
    __shared__ float As[128 * 33];     // 8*33 % 32 = 8 -> conflict-free bcast reads
    __shared__ float Bs[2 * 32 * 64];  // double buffered (cp.async)
    __shared__ int   wsum[4];

    int t  = threadIdx.x;
    int bx = blockIdx.x;

    if (bx < 128) {
        // ------------------------- GEMM role -------------------------
        int which = bx >> 6;
        int rb    = bx & 63;
        const float* A = which ? feat_a : feat;
        float*       C = which ? g_xaw1 : g_xw1;
        int row0 = rb * 128;
        int tx = t & 7, ty = t >> 3;

        u64 acc[8][4];
        #pragma unroll
        for (int i = 0; i < 8; i++)
            #pragma unroll
            for (int j = 0; j < 4; j++) acc[i][j] = 0ull;

        float4 areg[8];

        {   // prologue: tile 0
            #pragma unroll
            for (int i = 0; i < 8; i++) {
                int lin = t + i * 128;
                int r = lin >> 3, kq = lin & 7;
                areg[i] = *(const float4*)(A + (size_t)(row0 + r) * FIN + kq * 4);
            }
            #pragma unroll
            for (int i = 0; i < 4; i++) {
                int lin = t + i * 128;
                int k = lin >> 4, nq = lin & 15;
                cp16(&Bs[k * 64 + nq * 4], W1 + (size_t)k * FO + nq * 4, 16);
            }
            cpcommit();
            #pragma unroll
            for (int i = 0; i < 8; i++) {
                int lin = t + i * 128;
                int r = lin >> 3, kq = lin & 7;
                float* p = &As[r * 33 + kq * 4];
                p[0] = areg[i].x; p[1] = areg[i].y; p[2] = areg[i].z; p[3] = areg[i].w;
            }
        }

        int abase[8];
        #pragma unroll
        for (int i = 0; i < 8; i++) abase[i] = (ty * 8 + i) * 33;

        for (int kt = 0; kt < KT; kt++) {
            int buf = kt & 1;
            if (kt + 1 < KT) {
                int k0 = (kt + 1) * 32;
                #pragma unroll
                for (int i = 0; i < 8; i++) {
                    int lin = t + i * 128;
                    int r = lin >> 3, kq = lin & 7;
                    int gk = k0 + kq * 4;
                    areg[i] = (gk + 4 <= FIN) ? *(const float4*)(A + (size_t)(row0 + r) * FIN + gk)
                                              : make_float4(0.f, 0.f, 0.f, 0.f);
                }
                #pragma unroll
                for (int i = 0; i < 4; i++) {
                    int lin = t + i * 128;
                    int k = lin >> 4, nq = lin & 15;
                    cp16(&Bs[(buf ^ 1) * 2048 + k * 64 + nq * 4],
                         W1 + (size_t)(k0 + k) * FO + nq * 4, (k0 + k < FIN) ? 16 : 0);
                }
                cpcommit();
                asm volatile("cp.async.wait_group 1;");
            } else {
                asm volatile("cp.async.wait_group 0;");
            }
            __syncthreads();

            const float* bs = &Bs[buf * 2048];
            #pragma unroll 4
            for (int k = 0; k < 32; k++) {
                ulonglong2 q0 = *(const ulonglong2*)(bs + k * 64 + tx * 8);
                ulonglong2 q1 = *(const ulonglong2*)(bs + k * 64 + tx * 8 + 4);
                #pragma unroll
                for (int i = 0; i < 8; i++) {
                    u64 ad = dup2(As[abase[i] + k]);
                    ffma2(acc[i][0], ad, q0.x);
                    ffma2(acc[i][1], ad, q0.y);
                    ffma2(acc[i][2], ad, q1.x);
                    ffma2(acc[i][3], ad, q1.y);
                }
            }
            __syncthreads();
            if (kt + 1 < KT) {
                #pragma unroll
                for (int i = 0; i < 8; i++) {
                    int lin = t + i * 128;
                    int r = lin >> 3, kq = lin & 7;
                    float* p = &As[r * 33 + kq * 4];
                    p[0] = areg[i].x; p[1] = areg[i].y; p[2] = areg[i].z; p[3] = areg[i].w;
                }
            }
        }

        #pragma unroll
        for (int i = 0; i < 8; i++) {
            float2 a0 = unp(acc[i][0]), a1 = unp(acc[i][1]);
            float2 a2 = unp(acc[i][2]), a3 = unp(acc[i][3]);
            size_t r = row0 + ty * 8 + i;
            *(float4*)(C + r * FO + tx * 8)     = make_float4(a0.x, a0.y, a1.x, a1.y);
            *(float4*)(C + r * FO + tx * 8 + 4) = make_float4(a2.x, a2.y, a3.x, a3.y);
        }
    } else {
        // ------------------------- BUILD role -------------------------
        int bxx   = bx - 128;
        int which = bxx >> 13;
        int row   = bxx & (NN - 1);
        const float* mat = which ? gnm : adj;
        const float4* rp = (const float4*)(mat + (size_t)row * NN);

        // Coalesced: float4 index f = t + 128*q; warp lanes contiguous.
        u64 mask = 0ull;
        #pragma unroll
        for (int q = 0; q < 16; q++) {
            float4 v = rp[t + 128 * q];
            u64 m4 = (u64)((v.x != 0.f) | ((v.y != 0.f) << 1) |
                           ((v.z != 0.f) << 2) | ((v.w != 0.f) << 3));
            mask |= m4 << (q * 4);
        }
        int c = __popcll(mask);

        // warp inclusive scan
        int lane = t & 31, w = t >> 5;
        int x = c;
        #pragma unroll
        for (int d = 1; d < 32; d <<= 1) {
            int y = __shfl_up_sync(0xffffffffu, x, d);
            if (lane >= d) x += y;
        }
        if (lane == 31) wsum[w] = x;
        __syncthreads();
        int base = 0;
        #pragma unroll
        for (int i = 0; i < 4; i++) base += (i < w) ? wsum[i] : 0;
        int o = base + x - c;
        int total = wsum[0] + wsum[1] + wsum[2] + wsum[3];

        int* outl = (which ? g_gn_idx : g_adj_idx) + (size_t)row * CAP;
        u64 m = mask;
        int colbase = t * 4;
        while (m) {
            int b = __ffsll(m) - 1;
            int col = colbase + ((b >> 2) << 9) + (b & 3);   // 4t + 512*(b/4) + b%4
            if (o < CAP) outl[o] = col;
            o++;
            m &= m - 1;
        }
        if (t == 0) {
            if (which == 0) {
                int tot = total;
                if (tot < CAP) { outl[tot] = row; tot++; }   // self loop
                g_adj_cnt[row] = tot;
                g_dinv[row]    = rsqrtf((float)tot);
            } else {
                g_gn_cnt[row] = total;
            }
        }
    }
}

// ---------------------------------------------------------------------------
// z = P@XW1 ; emb = relu(z) ; emb_a = relu(P@XaW1).  2 rows/block, unroll-4.
// ---------------------------------------------------------------------------
__global__ void __launch_bounds__(128) spmm1_kernel(
    float* __restrict__ out_z, float* __restrict__ out_emb, float* __restrict__ out_emb_a)
{
    int t = threadIdx.x, h = t >> 6, tt = t & 63;
    int row = blockIdx.x * 2 + h;
    __shared__ int   sidx[2][CAP];
    __shared__ float sw[2][CAP];
    int cnt = g_adj_cnt[row];
    for (int k = tt; k < cnt; k += 64) {
        int j = g_adj_idx[row * CAP + k];
        sidx[h][k] = j * 64;
        sw[h][k]   = g_dinv[j];
    }
    __syncthreads();
    float a0 = 0.f, a1 = 0.f, a2 = 0.f, a3 = 0.f;
    float b0 = 0.f, b1 = 0.f, b2 = 0.f, b3 = 0.f;
    int k = 0;
    for (; k + 4 <= cnt; k += 4) {
        int j0 = sidx[h][k] + tt,     j1 = sidx[h][k + 1] + tt;
        int j2 = sidx[h][k + 2] + tt, j3 = sidx[h][k + 3] + tt;
        float w0 = sw[h][k], w1 = sw[h][k + 1], w2 = sw[h][k + 2], w3 = sw[h][k + 3];
        a0 += w0 * g_xw1[j0];  b0 += w0 * g_xaw1[j0];
        a1 += w1 * g_xw1[j1];  b1 += w1 * g_xaw1[j1];
        a2 += w2 * g_xw1[j2];  b2 += w2 * g_xaw1[j2];
        a3 += w3 * g_xw1[j3];  b3 += w3 * g_xaw1[j3];
    }
    for (; k < cnt; k++) {
        int j = sidx[h][k] + tt; float w = sw[h][k];
        a0 += w * g_xw1[j];  b0 += w * g_xaw1[j];
    }
    float di = g_dinv[row];
    float z  = di * ((a0 + a1) + (a2 + a3));
    float za = di * ((b0 + b1) + (b2 + b3));
    out_z[row * 64 + tt]     = z;
    out_emb[row * 64 + tt]   = fmaxf(z, 0.f);
    out_emb_a[row * 64 + tt] = fmaxf(za, 0.f);
}

// ---------------------------------------------------------------------------
// Fused: Pz = P@z ; readout (gv -> sigmoid) ; bilinear discriminator.
// ---------------------------------------------------------------------------
__global__ void __launch_bounds__(128) spmm2_readout_disc_kernel(
    const float* __restrict__ z, const float* __restrict__ emb,
    const float* __restrict__ emb_a, const float* __restrict__ W,
    const float* __restrict__ bptr,
    float* __restrict__ ret, float* __restrict__ ret_a)
{
    int t = threadIdx.x, h = t >> 6, tt = t & 63;
    int row = blockIdx.x * 2 + h;
    __shared__ int   sidx[2][CAP];
    __shared__ float sw[2][CAP];
    __shared__ float red[2][256];
    __shared__ float sg[2][64], sga[2][64], se[2][64], sea[2][64];

    // --- spmm2: Pz ---
    int cnt = g_adj_cnt[row];
    for (int k = tt; k < cnt; k += 64) {
        int j = g_adj_idx[row * CAP + k];
        sidx[h][k] = j * 64;
        sw[h][k]   = g_dinv[j];
    }
    __syncthreads();
    float p0 = 0.f, p1 = 0.f, p2 = 0.f, p3 = 0.f;
    int k = 0;
    for (; k + 4 <= cnt; k += 4) {
        p0 += sw[h][k]     * z[sidx[h][k]     + tt];
        p1 += sw[h][k + 1] * z[sidx[h][k + 1] + tt];
        p2 += sw[h][k + 2] * z[sidx[h][k + 2] + tt];
        p3 += sw[h][k + 3] * z[sidx[h][k + 3] + tt];
    }
    for (; k < cnt; k++) p0 += sw[h][k] * z[sidx[h][k] + tt];
    g_pz[row * 64 + tt] = g_dinv[row] * ((p0 + p1) + (p2 + p3));

    // --- readout ---
    int gcnt = g_gn_cnt[row];
    __syncthreads();
    for (int kk = tt; kk < gcnt; kk += 64) sidx[h][kk] = g_gn_idx[row * CAP + kk] * 64;
    __syncthreads();
    float s0 = 0.f, s1 = 0.f, s2 = 0.f, s3 = 0.f;
    float u0 = 0.f, u1 = 0.f, u2 = 0.f, u3 = 0.f;
    k = 0;
    for (; k + 4 <= gcnt; k += 4) {
        int j0 = sidx[h][k] + tt,     j1 = sidx[h][k + 1] + tt;
        int j2 = sidx[h][k + 2] + tt, j3 = sidx[h][k + 3] + tt;
        s0 += emb[j0];  u0 += emb_a[j0];
        s1 += emb[j1];  u1 += emb_a[j1];
        s2 += emb[j2];  u2 += emb_a[j2];
        s3 += emb[j3];  u3 += emb_a[j3];
    }
    for (; k < gcnt; k++) { int j = sidx[h][k] + tt; s0 += emb[j]; u0 += emb_a[j]; }
    float inv = 1.f / (float)gcnt;
    float gv  = ((s0 + s1) + (s2 + s3)) * inv;
    float gva = ((u0 + u1) + (u2 + u3)) * inv;

    red[h][tt] = gv * gv; __syncthreads();
    for (int s = 32; s >= 1; s >>= 1) { if (tt < s) red[h][tt] += red[h][tt + s]; __syncthreads(); }
    float n1 = sqrtf(red[h][0]); __syncthreads();
    red[h][tt] = gva * gva; __syncthreads();
    for (int s = 32; s >= 1; s >>= 1) { if (tt < s) red[h][tt] += red[h][tt + s]; __syncthreads(); }
    float n2 = sqrtf(red[h][0]);

    float x1 = gv  / fmaxf(n1, 1e-12f);
    float x2 = gva / fmaxf(n2, 1e-12f);
    sg[h][tt]  = 1.f / (1.f + expf(-x1));
    sga[h][tt] = 1.f / (1.f + expf(-x2));
    se[h][tt]  = emb[row * 64 + tt];
    sea[h][tt] = emb_a[row * 64 + tt];
    __syncthreads();

    // --- discriminator ---
    float v = 0.f, va = 0.f;
    #pragma unroll 8
    for (int d = 0; d < 64; d++) {
        float w = W[d * 64 + tt];
        v  += se[h][d]  * w;
        va += sea[h][d] * w;
    }
    red[h][tt]       = v  * sg[h][tt];
    red[h][64 + tt]  = va * sg[h][tt];
    red[h][128 + tt] = va * sga[h][tt];
    red[h][192 + tt] = v  * sga[h][tt];
    __syncthreads();
    for (int s = 32; s >= 1; s >>= 1) {
        if (tt < s) {
            red[h][tt]       += red[h][tt + s];
            red[h][64 + tt]  += red[h][64 + tt + s];
            red[h][128 + tt] += red[h][128 + tt + s];
            red[h][192 + tt] += red[h][192 + tt + s];
        }
        __syncthreads();
    }
    if (tt == 0) {
        float b = bptr[0];
        ret[row * 2 + 0]   = red[h][0]   + b;
        ret[row * 2 + 1]   = red[h][64]  + b;
        ret_a[row * 2 + 0] = red[h][128] + b;
        ret_a[row * 2 + 1] = red[h][192] + b;
    }
}

// ---------------------------------------------------------------------------
// h = Pz @ W2. M=8192 K=64 N=3000. 128x64 block tile, 128 thr, 8x8/thread.
// ---------------------------------------------------------------------------
__global__ void __launch_bounds__(128) gemm_h_kernel(const float* __restrict__ W2,
                                                     float* __restrict__ outh)
{
    __shared__ float As[128 * 65];
    __shared__ float Bs[64 * 64];
    int t = threadIdx.x;
    int row0 = blockIdx.x * 128;
    int n0   = blockIdx.y * 64;
    int tx = t & 7, ty = t >> 3;

    #pragma unroll
    for (int i = 0; i < 16; i++) {
        int lin = t + i * 128;
        int r = lin >> 4, kq = lin & 15;
        float4 v = *(const float4*)(g_pz + (size_t)(row0 + r) * 64 + kq * 4);
        float* p = &As[r * 65 + kq * 4];
        p[0] = v.x; p[1] = v.y; p[2] = v.z; p[3] = v.w;
    }
    #pragma unroll
    for (int i = 0; i < 8; i++) {
        int lin = t + i * 128;
        int kk = lin >> 4, nq = lin & 15;
        int col = n0 + nq * 4;
        float4 v = (col < FIN) ? *(const float4*)(W2 + (size_t)kk * FIN + col)
                               : make_float4(0.f, 0.f, 0.f, 0.f);
        *(float4*)(&Bs[kk * 64 + nq * 4]) = v;
    }
    __syncthreads();

    u64 acc[8][4];
    #pragma unroll
    for (int i = 0; i < 8; i++)
        #pragma unroll
        for (int j = 0; j < 4; j++) acc[i][j] = 0ull;

    int abase[8];
    #pragma unroll
    for (int i = 0; i < 8; i++) abase[i] = (ty * 8 + i) * 65;

    #pragma unroll 8
    for (int k = 0; k < 64; k++) {
        ulonglong2 q0 = *(const ulonglong2*)(&Bs[k * 64 + tx * 8]);
        ulonglong2 q1 = *(const ulonglong2*)(&Bs[k * 64 + tx * 8 + 4]);
        #pragma unroll
        for (int i = 0; i < 8; i++) {
            u64 ad = dup2(As[abase[i] + k]);
            ffma2(acc[i][0], ad, q0.x);
            ffma2(acc[i][1], ad, q0.y);
            ffma2(acc[i][2], ad, q1.x);
            ffma2(acc[i][3], ad, q1.y);
        }
    }

    int cb = n0 + tx * 8;
    if (cb < FIN) {
        #pragma unroll
        for (int i = 0; i < 8; i++) {
            float2 a0 = unp(acc[i][0]), a1 = unp(acc[i][1]);
            float2 a2 = unp(acc[i][2]), a3 = unp(acc[i][3]);
            size_t r = row0 + ty * 8 + i;
            *(float4*)(outh + r * FIN + cb)     = make_float4(a0.x, a0.y, a1.x, a1.y);
            *(float4*)(outh + r * FIN + cb + 4) = make_float4(a2.x, a2.y, a3.x, a3.y);
        }
    }
}

// ---------------------------------------------------------------------------
extern "C" void kernel_launch(void* const* d_in, const int* in_sizes, int n_in,
                              void* d_out, int out_size)
{
    const float* feat   = (const float*)d_in[0];
    const float* feat_a = (const float*)d_in[1];
    const float* adj    = (const float*)d_in[2];
    const float* gnm    = (const float*)d_in[3];
    const float* W1     = (const float*)d_in[4];
    const float* W2     = (const float*)d_in[5];
    const float* dW     = (const float*)d_in[6];
    const float* db     = (const float*)d_in[7];
    (void)in_sizes; (void)n_in; (void)out_size;

    float* out       = (float*)d_out;
    float* out_z     = out;                       // [8192,64]
    float* out_h     = out + 524288;              // [8192,3000]
    float* out_ret   = out + 25100288;            // [8192,2]
    float* out_ret_a = out + 25116672;            // [8192,2]
    float* out_emb   = out + 25133056;            // [8192,64]
    float* out_emb_a = out + 25657344;            // [8192,64]

    fused_build_gemm<<<128 + 2 * NN, 128>>>(feat, feat_a, W1, adj, gnm);
    spmm1_kernel<<<NN / 2, 128>>>(out_z, out_emb, out_emb_a);
    spmm2_readout_disc_kernel<<<NN / 2, 128>>>(out_z, out_emb, out_emb_a, dW, db,
                                               out_ret, out_ret_a);
    gemm_h_kernel<<<dim3(NN / 128, (FIN + 63) / 64), 128>>>(W2, out_h);
}

// round 8
// speedup vs baseline: 2.2407x; 1.6061x over previous
#include <cuda_runtime.h>
#include <cuda_bf16.h>
#include <math.h>
#include <stdint.h>

#define NN   8192
#define FIN  3000
#define FO   64
#define CAP  192
#define KC   94          // ceil(3000/32) K-chunks for feat GEMM
#define KPAD 3008

typedef unsigned long long u64;
typedef unsigned int       u32;

// ---------------- scratch ----------------
__device__ int   g_adj_idx[NN * CAP];
__device__ int   g_adj_cnt[NN];
__device__ float g_dinv[NN];
__device__ int   g_gn_idx[NN * CAP];
__device__ int   g_gn_cnt[NN];
__device__ float g_xw1[NN * FO];
__device__ float g_xaw1[NN * FO];
__device__ float g_pz[NN * FO];
__device__ __nv_bfloat16 g_w1t_hi[FO * KPAD];   // W1^T  [64][3008]
__device__ __nv_bfloat16 g_w1t_lo[FO * KPAD];
__device__ __nv_bfloat16 g_w2t_hi[3072 * FO];   // W2^T  [3072][64]
__device__ __nv_bfloat16 g_w2t_lo[3072 * FO];

// ---------------- mma.sync (sm_80+ PTX; fragment loads are plain LDS) ------
__device__ __forceinline__ void mmabf(float* d, const u32* a, const u32* b) {
    asm volatile("mma.sync.aligned.m16n8k16.row.col.f32.bf16.bf16.f32 "
                 "{%0,%1,%2,%3},{%4,%5,%6,%7},{%8,%9},{%0,%1,%2,%3};"
                 : "+f"(d[0]), "+f"(d[1]), "+f"(d[2]), "+f"(d[3])
                 : "r"(a[0]), "r"(a[1]), "r"(a[2]), "r"(a[3]), "r"(b[0]), "r"(b[1]));
}

// hi/lo bf16 split of 4 floats, packed as 2x(bf16x2)
__device__ __forceinline__ void split4(float4 v, uint2& hi, uint2& lo) {
    __nv_bfloat16 h0 = __float2bfloat16(v.x), h1 = __float2bfloat16(v.y);
    __nv_bfloat16 h2 = __float2bfloat16(v.z), h3 = __float2bfloat16(v.w);
    __nv_bfloat16 l0 = __float2bfloat16(v.x - __bfloat162float(h0));
    __nv_bfloat16 l1 = __float2bfloat16(v.y - __bfloat162float(h1));
    __nv_bfloat16 l2 = __float2bfloat16(v.z - __bfloat162float(h2));
    __nv_bfloat16 l3 = __float2bfloat16(v.w - __bfloat162float(h3));
    hi.x = ((u32)__bfloat16_as_ushort(h1) << 16) | __bfloat16_as_ushort(h0);
    hi.y = ((u32)__bfloat16_as_ushort(h3) << 16) | __bfloat16_as_ushort(h2);
    lo.x = ((u32)__bfloat16_as_ushort(l1) << 16) | __bfloat16_as_ushort(l0);
    lo.y = ((u32)__bfloat16_as_ushort(l3) << 16) | __bfloat16_as_ushort(l2);
}

// ---------------------------------------------------------------------------
// Prep: W1^T and W2^T as bf16 hi/lo, zero-padded.
// ---------------------------------------------------------------------------
__global__ void prep_kernel(const float* __restrict__ W1, const float* __restrict__ W2)
{
    int bx = blockIdx.x, t = threadIdx.x;
    if (bx < 752) {                 // w1t: 64 x 3008
        int idx = bx * 256 + t;
        int n = idx & 63, k = idx >> 6;
        float x = (k < FIN) ? W1[k * 64 + n] : 0.f;
        __nv_bfloat16 h = __float2bfloat16(x);
        __nv_bfloat16 l = __float2bfloat16(x - __bfloat162float(h));
        g_w1t_hi[n * KPAD + k] = h;
        g_w1t_lo[n * KPAD + k] = l;
    } else {                        // w2t: 3072 x 64
        int idx = (bx - 752) * 256 + t;
        int k = idx & 63, n = idx >> 6;
        float x = (n < FIN) ? W2[k * FIN + n] : 0.f;
        __nv_bfloat16 h = __float2bfloat16(x);
        __nv_bfloat16 l = __float2bfloat16(x - __bfloat162float(h));
        g_w2t_hi[n * 64 + k] = h;
        g_w2t_lo[n * 64 + k] = l;
    }
}

// ---------------------------------------------------------------------------
// Fused: blocks [0,128) = feat@W1 / feat_a@W1 via bf16-split mma.sync;
//        blocks [128, 128+2*NN) = adjacency / graph_neigh ELL builds.
// Tile 128x64, BK=32. Smem rows stride 80B (bank-rotating, conflict-free).
// B tile: each row = 32 bf16 = 64 B = FOUR uint4; 2 threads/row move TWO each.
// ---------------------------------------------------------------------------
__global__ void __launch_bounds__(256) fused_build_gemm(
    const float* __restrict__ feat, const float* __restrict__ feat_a,
    const float* __restrict__ adj, const float* __restrict__ gnm)
{
    __shared__ __align__(16) unsigned char s_ahi[10240];  // 128 rows x 80B
    __shared__ __align__(16) unsigned char s_alo[10240];
    __shared__ __align__(16) unsigned char s_bhi[5120];   // 64 rows x 80B
    __shared__ __align__(16) unsigned char s_blo[5120];
    __shared__ int wsum[8];

    int t  = threadIdx.x;
    int bx = blockIdx.x;

    if (bx < 128) {
        // ------------------- GEMM role -------------------
        int which = bx >> 6;
        int row0  = (bx & 63) * 128;
        const float* A = which ? feat_a : feat;
        float*       C = which ? g_xaw1 : g_xw1;

        int wid = t >> 5, lane = t & 31;
        int wm = wid & 3, wn = wid >> 2;     // 4 warps x 32 rows, 2 warps x 32 cols
        int fr = lane >> 2;                  // groupID
        int fcb = (lane & 3) * 4;            // k-pair byte offset

        float d[2][4][4];
        #pragma unroll
        for (int mi = 0; mi < 2; mi++)
            #pragma unroll
            for (int ni = 0; ni < 4; ni++)
                #pragma unroll
                for (int j = 0; j < 4; j++) d[mi][ni][j] = 0.f;

        // A-store mapping: 4 float4/thread
        int ar[4], aq[4];
        #pragma unroll
        for (int i = 0; i < 4; i++) { int lin = t + i * 256; ar[i] = lin >> 3; aq[i] = lin & 7; }
        // B: 2 threads/row, each moves 2 uint4 (32 B) -> full 64-B row covered
        int bi = t & 127, bn = bi >> 1, bhalf = bi & 1, bbuf = t >> 7;
        const __nv_bfloat16* bsrc = bbuf ? g_w1t_lo : g_w1t_hi;
        unsigned char* bdst = (bbuf ? s_blo : s_bhi) + bn * 80 + bhalf * 32;

        float4 pa[4]; uint4 pb0, pb1;
        #pragma unroll
        for (int i = 0; i < 4; i++)
            pa[i] = *(const float4*)(A + (size_t)(row0 + ar[i]) * FIN + aq[i] * 4);
        pb0 = *(const uint4*)(bsrc + (size_t)bn * KPAD + bhalf * 16);
        pb1 = *(const uint4*)(bsrc + (size_t)bn * KPAD + bhalf * 16 + 8);

        for (int c = 0; c < KC; c++) {
            #pragma unroll
            for (int i = 0; i < 4; i++) {
                uint2 hi, lo; split4(pa[i], hi, lo);
                *(uint2*)(s_ahi + ar[i] * 80 + aq[i] * 8) = hi;
                *(uint2*)(s_alo + ar[i] * 80 + aq[i] * 8) = lo;
            }
            *(uint4*)bdst        = pb0;
            *(uint4*)(bdst + 16) = pb1;
            __syncthreads();

            if (c + 1 < KC) {
                int k0 = (c + 1) * 32;
                #pragma unroll
                for (int i = 0; i < 4; i++) {
                    int gk = k0 + aq[i] * 4;
                    pa[i] = (gk + 4 <= FIN)
                        ? *(const float4*)(A + (size_t)(row0 + ar[i]) * FIN + gk)
                        : make_float4(0.f, 0.f, 0.f, 0.f);
                }
                pb0 = *(const uint4*)(bsrc + (size_t)bn * KPAD + k0 + bhalf * 16);
                pb1 = *(const uint4*)(bsrc + (size_t)bn * KPAD + k0 + bhalf * 16 + 8);
            }

            #pragma unroll
            for (int ks = 0; ks < 32; ks += 16) {
                int cb = fcb + ks * 2;
                u32 ahi[2][4], alo[2][4], bh[4][2], bl[4][2];
                #pragma unroll
                for (int mi = 0; mi < 2; mi++) {
                    int r0b = (wm * 32 + mi * 16 + fr) * 80 + cb;
                    ahi[mi][0] = *(const u32*)(s_ahi + r0b);
                    ahi[mi][1] = *(const u32*)(s_ahi + r0b + 8 * 80);
                    ahi[mi][2] = *(const u32*)(s_ahi + r0b + 16);
                    ahi[mi][3] = *(const u32*)(s_ahi + r0b + 8 * 80 + 16);
                    alo[mi][0] = *(const u32*)(s_alo + r0b);
                    alo[mi][1] = *(const u32*)(s_alo + r0b + 8 * 80);
                    alo[mi][2] = *(const u32*)(s_alo + r0b + 16);
                    alo[mi][3] = *(const u32*)(s_alo + r0b + 8 * 80 + 16);
                }
                #pragma unroll
                for (int ni = 0; ni < 4; ni++) {
                    int nb = (wn * 32 + ni * 8 + fr) * 80 + cb;
                    bh[ni][0] = *(const u32*)(s_bhi + nb);
                    bh[ni][1] = *(const u32*)(s_bhi + nb + 16);
                    bl[ni][0] = *(const u32*)(s_blo + nb);
                    bl[ni][1] = *(const u32*)(s_blo + nb + 16);
                }
                #pragma unroll
                for (int mi = 0; mi < 2; mi++)
                    #pragma unroll
                    for (int ni = 0; ni < 4; ni++) {
                        mmabf(d[mi][ni], ahi[mi], bh[ni]);
                        mmabf(d[mi][ni], ahi[mi], bl[ni]);
                        mmabf(d[mi][ni], alo[mi], bh[ni]);
                    }
            }
            __syncthreads();
        }

        #pragma unroll
        for (int mi = 0; mi < 2; mi++)
            #pragma unroll
            for (int ni = 0; ni < 4; ni++) {
                int r = row0 + wm * 32 + mi * 16 + fr;
                int cc = wn * 32 + ni * 8 + (lane & 3) * 2;
                *(float2*)(C + (size_t)r * FO + cc)       = make_float2(d[mi][ni][0], d[mi][ni][1]);
                *(float2*)(C + (size_t)(r + 8) * FO + cc) = make_float2(d[mi][ni][2], d[mi][ni][3]);
            }
    } else {
        // ------------------- BUILD role -------------------
        int bxx   = bx - 128;
        int which = bxx >> 13;
        int row   = bxx & (NN - 1);
        const float* mat = which ? gnm : adj;
        const float4* rp = (const float4*)(mat + (size_t)row * NN);

        u32 mask = 0u;
        #pragma unroll
        for (int q = 0; q < 8; q++) {
            float4 v = rp[t + 256 * q];
            u32 m4 = (u32)((v.x != 0.f) | ((v.y != 0.f) << 1) |
                           ((v.z != 0.f) << 2) | ((v.w != 0.f) << 3));
            mask |= m4 << (q * 4);
        }
        int c = __popc(mask);

        int lane = t & 31, w = t >> 5;
        int x = c;
        #pragma unroll
        for (int dd = 1; dd < 32; dd <<= 1) {
            int y = __shfl_up_sync(0xffffffffu, x, dd);
            if (lane >= dd) x += y;
        }
        if (lane == 31) wsum[w] = x;
        __syncthreads();
        int base = 0, total = 0;
        #pragma unroll
        for (int i = 0; i < 8; i++) { int s = wsum[i]; base += (i < w) ? s : 0; total += s; }
        int o = base + x - c;

        int* outl = (which ? g_gn_idx : g_adj_idx) + (size_t)row * CAP;
        u32 m = mask;
        int colbase = t * 4;
        while (m) {
            int b = __ffs(m) - 1;
            int col = colbase + ((b >> 2) << 10) + (b & 3);
            if (o < CAP) outl[o] = col;
            o++;
            m &= m - 1;
        }
        if (t == 0) {
            if (which == 0) {
                int tot = total;
                if (tot < CAP) { outl[tot] = row; tot++; }   // self loop
                g_adj_cnt[row] = tot;
                g_dinv[row]    = rsqrtf((float)tot);
            } else {
                g_gn_cnt[row] = total;
            }
        }
    }
}

// ---------------------------------------------------------------------------
// h = Pz @ W2 via bf16-split mma.sync. Tile 64x64, K=64. Smem stride 144B.
// ---------------------------------------------------------------------------
__global__ void __launch_bounds__(256) gemm_h_mma(float* __restrict__ outh)
{
    __shared__ __align__(16) unsigned char s_ahi[9216];   // 64 rows x 144B
    __shared__ __align__(16) unsigned char s_alo[9216];
    __shared__ __align__(16) unsigned char s_bhi[9216];
    __shared__ __align__(16) unsigned char s_blo[9216];

    int t = threadIdx.x;
    int wid = t >> 5, lane = t & 31;
    int wm = wid & 1, wn = wid >> 1;        // 2 warps x 32 rows, 4 warps x 16 cols
    int fr = lane >> 2;
    int fcb = (lane & 3) * 4;
    int row0 = blockIdx.x * 64;
    int n0   = blockIdx.y * 64;

    // A: 64 rows x 64 k fp32 -> hi/lo (4 float4/thread)
    #pragma unroll
    for (int i = 0; i < 4; i++) {
        int lin = t + i * 256;
        int r = lin >> 4, q = lin & 15;
        float4 v = *(const float4*)(g_pz + (size_t)(row0 + r) * 64 + q * 4);
        uint2 hi, lo; split4(v, hi, lo);
        *(uint2*)(s_ahi + r * 144 + q * 8) = hi;
        *(uint2*)(s_alo + r * 144 + q * 8) = lo;
    }
    // B: w2t rows [n0, n0+64), 64 k bf16 each (4 uint4/thread across hi/lo)
    #pragma unroll
    for (int i = 0; i < 4; i++) {
        int lin = t + i * 256;
        int buf = lin >> 9, rem = lin & 511;
        int n = rem >> 3, part = rem & 7;
        const __nv_bfloat16* src = buf ? g_w2t_lo : g_w2t_hi;
        uint4 v = *(const uint4*)(src + (size_t)(n0 + n) * 64 + part * 8);
        *(uint4*)((buf ? s_blo : s_bhi) + n * 144 + part * 16) = v;
    }
    __syncthreads();

    float d[2][2][4];
    #pragma unroll
    for (int mi = 0; mi < 2; mi++)
        #pragma unroll
        for (int ni = 0; ni < 2; ni++)
            #pragma unroll
            for (int j = 0; j < 4; j++) d[mi][ni][j] = 0.f;

    #pragma unroll
    for (int ks = 0; ks < 64; ks += 16) {
        int cb = fcb + ks * 2;
        u32 ahi[2][4], alo[2][4], bh[2][2], bl[2][2];
        #pragma unroll
        for (int mi = 0; mi < 2; mi++) {
            int r0b = (wm * 32 + mi * 16 + fr) * 144 + cb;
            ahi[mi][0] = *(const u32*)(s_ahi + r0b);
            ahi[mi][1] = *(const u32*)(s_ahi + r0b + 8 * 144);
            ahi[mi][2] = *(const u32*)(s_ahi + r0b + 16);
            ahi[mi][3] = *(const u32*)(s_ahi + r0b + 8 * 144 + 16);
            alo[mi][0] = *(const u32*)(s_alo + r0b);
            alo[mi][1] = *(const u32*)(s_alo + r0b + 8 * 144);
            alo[mi][2] = *(const u32*)(s_alo + r0b + 16);
            alo[mi][3] = *(const u32*)(s_alo + r0b + 8 * 144 + 16);
        }
        #pragma unroll
        for (int ni = 0; ni < 2; ni++) {
            int nb = (wn * 16 + ni * 8 + fr) * 144 + cb;
            bh[ni][0] = *(const u32*)(s_bhi + nb);
            bh[ni][1] = *(const u32*)(s_bhi + nb + 16);
            bl[ni][0] = *(const u32*)(s_blo + nb);
            bl[ni][1] = *(const u32*)(s_blo + nb + 16);
        }
        #pragma unroll
        for (int mi = 0; mi < 2; mi++)
            #pragma unroll
            for (int ni = 0; ni < 2; ni++) {
                mmabf(d[mi][ni], ahi[mi], bh[ni]);
                mmabf(d[mi][ni], ahi[mi], bl[ni]);
                mmabf(d[mi][ni], alo[mi], bh[ni]);
            }
    }

    #pragma unroll
    for (int mi = 0; mi < 2; mi++)
        #pragma unroll
        for (int ni = 0; ni < 2; ni++) {
            int r = row0 + wm * 32 + mi * 16 + fr;
            int cc = n0 + wn * 16 + ni * 8 + (lane & 3) * 2;
            if (cc < FIN) {
                *(float2*)(outh + (size_t)r * FIN + cc)       = make_float2(d[mi][ni][0], d[mi][ni][1]);
                *(float2*)(outh + (size_t)(r + 8) * FIN + cc) = make_float2(d[mi][ni][2], d[mi][ni][3]);
            }
        }
}

// ---------------------------------------------------------------------------
// z = P@XW1 ; emb = relu(z) ; emb_a = relu(P@XaW1).  2 rows/block, unroll-4.
// ---------------------------------------------------------------------------
__global__ void __launch_bounds__(128) spmm1_kernel(
    float* __restrict__ out_z, float* __restrict__ out_emb, float* __restrict__ out_emb_a)
{
    int t = threadIdx.x, h = t >> 6, tt = t & 63;
    int row = blockIdx.x * 2 + h;
    __shared__ int   sidx[2][CAP];
    __shared__ float sw[2][CAP];
    int cnt = g_adj_cnt[row];
    for (int k = tt; k < cnt; k += 64) {
        int j = g_adj_idx[row * CAP + k];
        sidx[h][k] = j * 64;
        sw[h][k]   = g_dinv[j];
    }
    __syncthreads();
    float a0 = 0.f, a1 = 0.f, a2 = 0.f, a3 = 0.f;
    float b0 = 0.f, b1 = 0.f, b2 = 0.f, b3 = 0.f;
    int k = 0;
    for (; k + 4 <= cnt; k += 4) {
        int j0 = sidx[h][k] + tt,     j1 = sidx[h][k + 1] + tt;
        int j2 = sidx[h][k + 2] + tt, j3 = sidx[h][k + 3] + tt;
        float w0 = sw[h][k], w1 = sw[h][k + 1], w2 = sw[h][k + 2], w3 = sw[h][k + 3];
        a0 += w0 * g_xw1[j0];  b0 += w0 * g_xaw1[j0];
        a1 += w1 * g_xw1[j1];  b1 += w1 * g_xaw1[j1];
        a2 += w2 * g_xw1[j2];  b2 += w2 * g_xaw1[j2];
        a3 += w3 * g_xw1[j3];  b3 += w3 * g_xaw1[j3];
    }
    for (; k < cnt; k++) {
        int j = sidx[h][k] + tt; float w = sw[h][k];
        a0 += w * g_xw1[j];  b0 += w * g_xaw1[j];
    }
    float di = g_dinv[row];
    float z  = di * ((a0 + a1) + (a2 + a3));
    float za = di * ((b0 + b1) + (b2 + b3));
    out_z[row * 64 + tt]     = z;
    out_emb[row * 64 + tt]   = fmaxf(z, 0.f);
    out_emb_a[row * 64 + tt] = fmaxf(za, 0.f);
}

// ---------------------------------------------------------------------------
// Fused: Pz = P@z ; readout ; bilinear discriminator. 2 rows/block.
// ---------------------------------------------------------------------------
__global__ void __launch_bounds__(128) spmm2_readout_disc_kernel(
    const float* __restrict__ z, const float* __restrict__ emb,
    const float* __restrict__ emb_a, const float* __restrict__ W,
    const float* __restrict__ bptr,
    float* __restrict__ ret, float* __restrict__ ret_a)
{
    int t = threadIdx.x, h = t >> 6, tt = t & 63;
    int row = blockIdx.x * 2 + h;
    __shared__ int   sidx[2][CAP];
    __shared__ float sw[2][CAP];
    __shared__ float red[2][256];
    __shared__ float sg[2][64], sga[2][64], se[2][64], sea[2][64];

    int cnt = g_adj_cnt[row];
    for (int k = tt; k < cnt; k += 64) {
        int j = g_adj_idx[row * CAP + k];
        sidx[h][k] = j * 64;
        sw[h][k]   = g_dinv[j];
    }
    __syncthreads();
    float p0 = 0.f, p1 = 0.f, p2 = 0.f, p3 = 0.f;
    int k = 0;
    for (; k + 4 <= cnt; k += 4) {
        p0 += sw[h][k]     * z[sidx[h][k]     + tt];
        p1 += sw[h][k + 1] * z[sidx[h][k + 1] + tt];
        p2 += sw[h][k + 2] * z[sidx[h][k + 2] + tt];
        p3 += sw[h][k + 3] * z[sidx[h][k + 3] + tt];
    }
    for (; k < cnt; k++) p0 += sw[h][k] * z[sidx[h][k] + tt];
    g_pz[row * 64 + tt] = g_dinv[row] * ((p0 + p1) + (p2 + p3));

    int gcnt = g_gn_cnt[row];
    __syncthreads();
    for (int kk = tt; kk < gcnt; kk += 64) sidx[h][kk] = g_gn_idx[row * CAP + kk] * 64;
    __syncthreads();
    float s0 = 0.f, s1 = 0.f, s2 = 0.f, s3 = 0.f;
    float u0 = 0.f, u1 = 0.f, u2 = 0.f, u3 = 0.f;
    k = 0;
    for (; k + 4 <= gcnt; k += 4) {
        int j0 = sidx[h][k] + tt,     j1 = sidx[h][k + 1] + tt;
        int j2 = sidx[h][k + 2] + tt, j3 = sidx[h][k + 3] + tt;
        s0 += emb[j0];  u0 += emb_a[j0];
        s1 += emb[j1];  u1 += emb_a[j1];
        s2 += emb[j2];  u2 += emb_a[j2];
        s3 += emb[j3];  u3 += emb_a[j3];
    }
    for (; k < gcnt; k++) { int j = sidx[h][k] + tt; s0 += emb[j]; u0 += emb_a[j]; }
    float inv = 1.f / (float)gcnt;
    float gv  = ((s0 + s1) + (s2 + s3)) * inv;
    float gva = ((u0 + u1) + (u2 + u3)) * inv;

    red[h][tt] = gv * gv; __syncthreads();
    for (int s = 32; s >= 1; s >>= 1) { if (tt < s) red[h][tt] += red[h][tt + s]; __syncthreads(); }
    float n1 = sqrtf(red[h][0]); __syncthreads();
    red[h][tt] = gva * gva; __syncthreads();
    for (int s = 32; s >= 1; s >>= 1) { if (tt < s) red[h][tt] += red[h][tt + s]; __syncthreads(); }
    float n2 = sqrtf(red[h][0]);

    float x1 = gv  / fmaxf(n1, 1e-12f);
    float x2 = gva / fmaxf(n2, 1e-12f);
    sg[h][tt]  = 1.f / (1.f + expf(-x1));
    sga[h][tt] = 1.f / (1.f + expf(-x2));
    se[h][tt]  = emb[row * 64 + tt];
    sea[h][tt] = emb_a[row * 64 + tt];
    __syncthreads();

    float v = 0.f, va = 0.f;
    #pragma unroll 8
    for (int dd = 0; dd < 64; dd++) {
        float w = W[dd * 64 + tt];
        v  += se[h][dd]  * w;
        va += sea[h][dd] * w;
    }
    red[h][tt]       = v  * sg[h][tt];
    red[h][64 + tt]  = va * sg[h][tt];
    red[h][128 + tt] = va * sga[h][tt];
    red[h][192 + tt] = v  * sga[h][tt];
    __syncthreads();
    for (int s = 32; s >= 1; s >>= 1) {
        if (tt < s) {
            red[h][tt]       += red[h][tt + s];
            red[h][64 + tt]  += red[h][64 + tt + s];
            red[h][128 + tt] += red[h][128 + tt + s];
            red[h][192 + tt] += red[h][192 + tt + s];
        }
        __syncthreads();
    }
    if (tt == 0) {
        float b = bptr[0];
        ret[row * 2 + 0]   = red[h][0]   + b;
        ret[row * 2 + 1]   = red[h][64]  + b;
        ret_a[row * 2 + 0] = red[h][128] + b;
        ret_a[row * 2 + 1] = red[h][192] + b;
    }
}

// ---------------------------------------------------------------------------
extern "C" void kernel_launch(void* const* d_in, const int* in_sizes, int n_in,
                              void* d_out, int out_size)
{
    const float* feat   = (const float*)d_in[0];
    const float* feat_a = (const float*)d_in[1];
    const float* adj    = (const float*)d_in[2];
    const float* gnm    = (const float*)d_in[3];
    const float* W1     = (const float*)d_in[4];
    const float* W2     = (const float*)d_in[5];
    const float* dW     = (const float*)d_in[6];
    const float* db     = (const float*)d_in[7];
    (void)in_sizes; (void)n_in; (void)out_size;

    float* out       = (float*)d_out;
    float* out_z     = out;                       // [8192,64]
    float* out_h     = out + 524288;              // [8192,3000]
    float* out_ret   = out + 25100288;            // [8192,2]
    float* out_ret_a = out + 25116672;            // [8192,2]
    float* out_emb   = out + 25133056;            // [8192,64]
    float* out_emb_a = out + 25657344;            // [8192,64]

    prep_kernel<<<1520, 256>>>(W1, W2);
    fused_build_gemm<<<128 + 2 * NN, 256>>>(feat, feat_a, adj, gnm);
    spmm1_kernel<<<NN / 2, 128>>>(out_z, out_emb, out_emb_a);
    spmm2_readout_disc_kernel<<<NN / 2, 128>>>(out_z, out_emb, out_emb_a, dW, db,
                                               out_ret, out_ret_a);
    gemm_h_mma<<<dim3(128, 47), 256>>>(out_h);
}